// round 14
// baseline (speedup 1.0000x reference)
#include <cuda_runtime.h>

#define NBATCH 16

__device__ float g_h1[NBATCH * 128 * 128 * 128];
__device__ float g_h2[NBATCH * 256 * 64 * 64];
__device__ float g_g1[NBATCH * 256 * 64 * 64];
__device__ float g_g2[NBATCH * 128 * 128 * 128];
__device__ float g_ze[NBATCH * 64 * 32 * 32];
__device__ float g_zq[NBATCH * 64 * 32 * 32];
__device__ float g_if[16384];
__device__ float g_wt1[128 * 3 * 16];
__device__ float2 g_w2s[16 * 128 * 256];
__device__ float2 g_w3s[16 * 256 * 64];
__device__ float2 g_d2s[16 * 256 * 128];
__device__ float2 g_d1s[16 * 64 * 256];

__device__ __forceinline__ void tf32split(float v, unsigned& hi, unsigned& lo) {
    unsigned h;
    asm("cvt.rna.tf32.f32 %0,%1;" : "=r"(h) : "f"(v));
    float l = v - __uint_as_float(h);
    unsigned lw;
    asm("cvt.rna.tf32.f32 %0,%1;" : "=r"(lw) : "f"(l));
    hi = h; lo = lw;
}
__device__ __forceinline__ unsigned tf32cvt(float v) {
    unsigned h;
    asm("cvt.rna.tf32.f32 %0,%1;" : "=r"(h) : "f"(v));
    return h;
}
__device__ __forceinline__ float2 splitpack(float v) {
    unsigned h, l;
    tf32split(v, h, l);
    return make_float2(__uint_as_float(h), __uint_as_float(l));
}
__device__ __forceinline__ void mma8(float* c, const unsigned* a, unsigned b0, unsigned b1) {
    asm("mma.sync.aligned.m16n8k8.row.col.f32.tf32.tf32.f32 "
        "{%0,%1,%2,%3},{%4,%5,%6,%7},{%8,%9},{%0,%1,%2,%3};"
        : "+f"(c[0]), "+f"(c[1]), "+f"(c[2]), "+f"(c[3])
        : "r"(a[0]), "r"(a[1]), "r"(a[2]), "r"(a[3]), "r"(b0), "r"(b1));
}
__device__ __forceinline__ void cp_async8(unsigned dst, const void* src) {
    asm volatile("cp.async.ca.shared.global [%0], [%1], 8;\n" :: "r"(dst), "l"(src));
}
__device__ __forceinline__ void cp_async4_z(unsigned dst, const void* src, bool pred) {
    int sz = pred ? 4 : 0;
    asm volatile("cp.async.ca.shared.global [%0], [%1], 4, %2;\n" :: "r"(dst), "l"(src), "r"(sz));
}
__device__ __forceinline__ void cp_commit() { asm volatile("cp.async.commit_group;\n"); }
template <int N> __device__ __forceinline__ void cp_wait() {
    asm volatile("cp.async.wait_group %0;\n" :: "n"(N));
}

// -------- weight transforms --------------------------------------------------
__global__ void wtrans(const float* __restrict__ w, float* __restrict__ wo, int Cout, int Cin) {
    int idx = blockIdx.x * 256 + threadIdx.x;
    int total = Cout * Cin * 16;
    if (idx < total) {
        int t = idx & 15, rest = idx >> 4;
        int ic = rest % Cin, oc = rest / Cin;
        wo[(ic * Cout + oc) * 16 + t] = w[idx];
    }
}
__global__ void wsplit2t(const float* __restrict__ w, float2* __restrict__ wo) {
    int idx = blockIdx.x * 256 + threadIdx.x;
    int t = idx & 15, ic = (idx >> 4) & 127, oc = idx >> 11;
    wo[(t * 128 + ic) * 256 + oc] = splitpack(w[idx]);
}
__global__ void wsplit3(const float* __restrict__ w, float2* __restrict__ wo) {
    int idx = blockIdx.x * 256 + threadIdx.x;
    int t = idx & 15, ic = (idx >> 4) & 255, oc = idx >> 12;
    wo[(t * 256 + ic) * 64 + oc] = splitpack(w[idx]);
}
__global__ void wsplitD2(const float* __restrict__ w, float2* __restrict__ wo) {
    int idx = blockIdx.x * 256 + threadIdx.x;
    int t = idx & 15, oc = (idx >> 4) & 127, ic = idx >> 11;
    wo[(t * 256 + ic) * 128 + oc] = splitpack(w[idx]);
}
__global__ void wsplitD1(const float* __restrict__ w, float2* __restrict__ wo) {
    int idx = blockIdx.x * 256 + threadIdx.x;
    int t = idx & 15, oc = (idx >> 4) & 255, ic = idx >> 12;
    wo[(t * 64 + ic) * 256 + oc] = splitpack(w[idx]);
}

// ============================================================================
// conv2 MMA (3-term): 1 output row x 64 cols x 128 oc per CTA (grid 2048).
// ============================================================================
#define C2_WS2 (4 * 8 * 132)
#define C2_INS (8 * 4 * 132)
#define C2_SMEM ((4 * C2_WS2 + C2_INS) * 4)
__global__ __launch_bounds__(256, 2)
void conv2_mma(const float* __restrict__ in, const float2* __restrict__ wt,
               const float* __restrict__ bias, float* __restrict__ out) {
    extern __shared__ float sm[];
    float2* ws0 = (float2*)sm;
    float* ins = sm + 4 * C2_WS2;
    unsigned ws_base = (unsigned)__cvta_generic_to_shared(ws0);
    unsigned in_base = (unsigned)__cvta_generic_to_shared(ins);

    const int y0  = blockIdx.x;              // single output row
    const int ocb = blockIdx.y * 128;
    const int b   = blockIdx.z;

    const int tid  = threadIdx.x;
    const int wid  = tid >> 5;
    const int lane = tid & 31;
    const int wm   = wid >> 2;
    const int xb   = (wid & 3) * 16;
    const int lq   = lane >> 2;
    const int lr   = lane & 3;

    float acc[4][2][4];
#pragma unroll
    for (int mt = 0; mt < 4; mt++)
#pragma unroll
        for (int nt = 0; nt < 2; nt++)
#pragma unroll
            for (int i = 0; i < 4; i++) acc[mt][nt][i] = 0.f;

    const int iy0 = 2 * y0 - 1;
    const float* inB = in + ((size_t)b * 128) * 128 * 128;

    auto stage_in = [&](int ch) {
        for (int idx = tid; idx < 8 * 4 * 132; idx += 256) {
            int icl = idx / 528;
            int rem = idx - icl * 528;
            int r = rem / 132, cc = rem - r * 132;
            int iy = iy0 + r, ix = cc - 1;
            bool ok = (unsigned)iy < 128u && (unsigned)ix < 128u;
            const float* src = inB + ((size_t)(ch * 8 + icl) * 128 + iy) * 128 + ix;
            cp_async4_z(in_base + (unsigned)idx * 4u, src, ok);
        }
        cp_commit();
    };
    auto stage_w = [&](int c, int buf) {
        const int tg = c & 3, ch = c >> 2;
#pragma unroll
        for (int i = 0; i < 16; i++) {
            int idx = tid + i * 256;
            int oc = idx & 127, icl = (idx >> 7) & 7, tl = idx >> 10;
            const float2* src =
                wt + ((size_t)((tg * 4 + tl) * 128 + ch * 8 + icl)) * 256 + ocb + oc;
            cp_async8(ws_base + (unsigned)(buf * C2_WS2 + (tl * 8 + icl) * 132 + oc) * 8u, src);
        }
        cp_commit();
    };

    stage_in(0);
    stage_w(0, 0);
    for (int c = 0; c < 64; c++) {
        const int ch = c >> 2, tg = c & 3;
        if (tg == 0 && c > 0) stage_in(ch);
        if (c < 63) { stage_w(c + 1, (c + 1) & 1); cp_wait<1>(); }
        else cp_wait<0>();
        __syncthreads();

        const float2* ws = ws0 + (c & 1) * C2_WS2;
#pragma unroll
        for (int tapl = 0; tapl < 4; tapl++) {
            const int ky = tg, kx = tapl;
            unsigned ahi[4][4], alo[4][4];
#pragma unroll
            for (int mt = 0; mt < 4; mt++) {
                const float2* ap = &ws[(tapl * 8 + lr) * 132 + wm * 64 + mt * 16 + lq];
                float2 p0 = ap[0], p1 = ap[8], p2 = ap[4 * 132], p3 = ap[4 * 132 + 8];
                ahi[mt][0] = __float_as_uint(p0.x); alo[mt][0] = __float_as_uint(p0.y);
                ahi[mt][1] = __float_as_uint(p1.x); alo[mt][1] = __float_as_uint(p1.y);
                ahi[mt][2] = __float_as_uint(p2.x); alo[mt][2] = __float_as_uint(p2.y);
                ahi[mt][3] = __float_as_uint(p3.x); alo[mt][3] = __float_as_uint(p3.y);
            }
#pragma unroll
            for (int nt = 0; nt < 2; nt++) {
                const int ox = xb + nt * 8 + lq;
                const float* bp = &ins[lr * 528 + ky * 132 + 2 * ox + kx];
                float rb0 = bp[0], rb1 = bp[4 * 528];
                unsigned bh0, bl0, bh1, bl1;
                tf32split(rb0, bh0, bl0);
                tf32split(rb1, bh1, bl1);
#pragma unroll
                for (int mt = 0; mt < 4; mt++) {
                    mma8(acc[mt][nt], ahi[mt], bh0, bh1);
                    mma8(acc[mt][nt], ahi[mt], bl0, bl1);
                    mma8(acc[mt][nt], alo[mt], bh0, bh1);
                }
            }
        }
        __syncthreads();
    }

#pragma unroll
    for (int mt = 0; mt < 4; mt++) {
        const int oc = ocb + wm * 64 + mt * 16 + lq;
        const float b0v = bias[oc], b1v = bias[oc + 8];
#pragma unroll
        for (int nt = 0; nt < 2; nt++) {
            const int ox = xb + nt * 8 + 2 * lr;
            float* o0 = out + (((size_t)b * 256 + oc) * 64 + y0) * 64 + ox;
            float* o1 = o0 + (size_t)8 * 64 * 64;
            *(float2*)o0 = make_float2(fmaxf(acc[mt][nt][0] + b0v, 0.f),
                                       fmaxf(acc[mt][nt][1] + b0v, 0.f));
            *(float2*)o1 = make_float2(fmaxf(acc[mt][nt][2] + b1v, 0.f),
                                       fmaxf(acc[mt][nt][3] + b1v, 0.f));
        }
    }
}

// ============================================================================
// conv3 MMA (3-term, R11 unchanged)
// ============================================================================
#define C3_WS2 (4 * 8 * 68)
#define C3_INS (8 * 18 * 68)
#define C3_SMEM ((4 * C3_WS2 + 2 * C3_INS) * 4)
__global__ __launch_bounds__(256, 2)
void conv3_mma(const float* __restrict__ in, const float2* __restrict__ wt,
               float* __restrict__ outp) {
    extern __shared__ float sm[];
    float2* ws0 = (float2*)sm;
    float* ins0 = sm + 4 * C3_WS2;
    unsigned ws_base = (unsigned)__cvta_generic_to_shared(ws0);
    unsigned in_base = (unsigned)__cvta_generic_to_shared(ins0);
    const int r0 = blockIdx.x * 8;
    const int b = blockIdx.z >> 2, slab = blockIdx.z & 3;
    const int tid = threadIdx.x, w = tid >> 5, lane = tid & 31;
    const int lq = lane >> 2, lr = lane & 3;
    float acc[4][4][4];
#pragma unroll
    for (int mt = 0; mt < 4; mt++)
#pragma unroll
        for (int nt = 0; nt < 4; nt++)
#pragma unroll
            for (int i = 0; i < 4; i++) acc[mt][nt][i] = 0.f;
    const int iy0 = r0 * 2 - 1;
    const float* inB = in + ((size_t)b * 256 + slab * 64) * 64 * 64;
    auto stage_in3 = [&](int ch) {
        const int ib = ch & 1;
        for (int idx = tid; idx < 8 * 18 * 66; idx += 256) {
            int icl = idx / 1188, rem = idx - icl * 1188;
            int r = rem / 66, cc = rem - r * 66;
            int iy = iy0 + r, ix = cc - 1;
            bool ok = (unsigned)iy < 64u && (unsigned)ix < 64u;
            const float* src = inB + ((size_t)(ch * 8 + icl) * 64 + iy) * 64 + ix;
            cp_async4_z(in_base + (unsigned)(ib * C3_INS + icl * 1224 + r * 68 + cc) * 4u, src, ok);
        }
    };
    auto stage_w3 = [&](int c, int buf) {
        const int tg = c & 3, ch = c >> 2;
#pragma unroll
        for (int i = 0; i < 8; i++) {
            int idx = tid + i * 256;
            int oc = idx & 63, icl = (idx >> 6) & 7, tl = idx >> 9;
            const float2* src = wt + ((size_t)((tg * 4 + tl) * 256 + slab * 64 + ch * 8 + icl)) * 64 + oc;
            cp_async8(ws_base + (unsigned)(buf * C3_WS2 + (tl * 8 + icl) * 68 + oc) * 8u, src);
        }
    };
    stage_in3(0);
    stage_w3(0, 0);
    cp_commit();
    for (int c = 0; c < 32; c++) {
        if (c < 31) {
            if (((c + 1) & 3) == 0) stage_in3((c + 1) >> 2);
            stage_w3(c + 1, (c + 1) & 1);
            cp_commit();
            cp_wait<1>();
        } else cp_wait<0>();
        __syncthreads();
        const int tg = c & 3;
        const float2* ws = ws0 + (c & 1) * C3_WS2;
        const float* ins = ins0 + ((c >> 2) & 1) * C3_INS;
#pragma unroll
        for (int tapl = 0; tapl < 4; tapl++) {
            const int ky = tg, kx = tapl;
            unsigned ahi[4][4], alo[4][4];
#pragma unroll
            for (int mt = 0; mt < 4; mt++) {
                const float2* ap = &ws[(tapl * 8 + lr) * 68 + mt * 16 + lq];
                float2 p0 = ap[0], p1 = ap[8], p2 = ap[4 * 68], p3 = ap[4 * 68 + 8];
                ahi[mt][0] = __float_as_uint(p0.x); alo[mt][0] = __float_as_uint(p0.y);
                ahi[mt][1] = __float_as_uint(p1.x); alo[mt][1] = __float_as_uint(p1.y);
                ahi[mt][2] = __float_as_uint(p2.x); alo[mt][2] = __float_as_uint(p2.y);
                ahi[mt][3] = __float_as_uint(p3.x); alo[mt][3] = __float_as_uint(p3.y);
            }
#pragma unroll
            for (int nt = 0; nt < 4; nt++) {
                const int col = nt * 8 + lq;
                const float* bp = &ins[lr * 1224 + (2 * w + ky) * 68 + 2 * col + kx];
                float rb0 = bp[0], rb1 = bp[4 * 1224];
                unsigned bh0, bl0, bh1, bl1;
                tf32split(rb0, bh0, bl0);
                tf32split(rb1, bh1, bl1);
#pragma unroll
                for (int mt = 0; mt < 4; mt++) {
                    mma8(acc[mt][nt], ahi[mt], bh0, bh1);
                    mma8(acc[mt][nt], ahi[mt], bl0, bl1);
                    mma8(acc[mt][nt], alo[mt], bh0, bh1);
                }
            }
        }
        __syncthreads();
    }
    const int NZ = NBATCH * 64 * 32 * 32;
    float* part = outp + (size_t)slab * NZ;
    const int row = r0 + w;
#pragma unroll
    for (int mt = 0; mt < 4; mt++) {
        const int oc = mt * 16 + lq;
#pragma unroll
        for (int nt = 0; nt < 4; nt++) {
            float* o0 = part + (((size_t)b * 64 + oc) * 32 + row) * 32 + nt * 8 + 2 * lr;
            float* o1 = o0 + (size_t)8 * 32 * 32;
            *(float2*)o0 = make_float2(acc[mt][nt][0], acc[mt][nt][1]);
            *(float2*)o1 = make_float2(acc[mt][nt][2], acc[mt][nt][3]);
        }
    }
}

__global__ void addparts(const float* __restrict__ p, const float* __restrict__ bias,
                         float* __restrict__ ze) {
    const int S = NBATCH * 64 * 32 * 32;
    int i = blockIdx.x * 256 + threadIdx.x;
    float v = p[i] + p[i + S] + p[i + 2 * S] + p[i + 3 * S];
    ze[i] = v + bias[(i >> 10) & 63];
}

// ============================================================================
// dconv MMA (1-term tf32, R11 unchanged)
// ============================================================================
#define D_WS2 (4 * 8 * 132)
template <int CIN, int HIN>
__global__ __launch_bounds__(256, 2)
void dconv_mma(const float* __restrict__ in, const float2* __restrict__ wt,
               const float* __restrict__ bias, float* __restrict__ out,
               int Cout, int nOcb) {
    const int WROW = HIN + 2;
    const int ISTR = HIN + 4;
    const int IBUF = 8 * 3 * ISTR;
    extern __shared__ float sm[];
    float2* ws0 = (float2*)sm;
    float* ins0 = sm + 4 * D_WS2;
    unsigned ws_base = (unsigned)__cvta_generic_to_shared(ws0);
    unsigned in_base = (unsigned)__cvta_generic_to_shared(ins0);
    const int y0 = blockIdx.x * 2;
    const int py = blockIdx.y >> 1, px = blockIdx.y & 1;
    const int b = blockIdx.z / nOcb;
    const int ocb = (blockIdx.z % nOcb) * 128;
    const int tid = threadIdx.x, wid = tid >> 5, lane = tid & 31;
    const int wm = wid >> 2, wn = wid & 3;
    const int yl = wn >> 1, xb = (wn & 1) * (HIN / 2);
    const int lq = lane >> 2, lr = lane & 3;
    const int NT = HIN / 16, NCH = CIN / 8;
    float acc[4][4][4];
#pragma unroll
    for (int mt = 0; mt < 4; mt++)
#pragma unroll
        for (int nt = 0; nt < 4; nt++)
#pragma unroll
            for (int i = 0; i < 4; i++) acc[mt][nt][i] = 0.f;
    const float* inB = in + ((size_t)b * CIN) * HIN * HIN;
    auto stage = [&](int ch, int buf) {
        for (int idx = tid; idx < 8 * 3 * WROW; idx += 256) {
            int icl = idx / (3 * WROW);
            int rem = idx - icl * 3 * WROW;
            int r = rem / WROW, s = rem - r * WROW;
            int iy = y0 + py - 1 + r;
            int ix = px - 1 + s;
            bool ok = (unsigned)iy < (unsigned)HIN && (unsigned)ix < (unsigned)HIN;
            const float* src = inB + ((size_t)(ch * 8 + icl) * HIN + iy) * HIN + ix;
            cp_async4_z(in_base + (unsigned)(buf * IBUF + (icl * 3 + r) * ISTR + s) * 4u, src, ok);
        }
#pragma unroll
        for (int i = 0; i < 16; i++) {
            int idx = tid + i * 256;
            int oc = idx & 127, icl = (idx >> 7) & 7, tl = idx >> 10;
            int a = tl >> 1, c2 = tl & 1;
            int t = (1 - py + 2 * a) * 4 + (1 - px + 2 * c2);
            const float2* src = wt + ((size_t)(t * CIN + ch * 8 + icl)) * Cout + ocb + oc;
            cp_async8(ws_base + (unsigned)(buf * D_WS2 + (tl * 8 + icl) * 132 + oc) * 8u, src);
        }
        cp_commit();
    };
    stage(0, 0);
    for (int ch = 0; ch < NCH; ch++) {
        if (ch + 1 < NCH) { stage(ch + 1, (ch + 1) & 1); cp_wait<1>(); }
        else cp_wait<0>();
        __syncthreads();
        const float2* ws = ws0 + (ch & 1) * D_WS2;
        const float* ins = ins0 + (ch & 1) * IBUF;
#pragma unroll
        for (int tl = 0; tl < 4; tl++) {
            const int a = tl >> 1, c = tl & 1;
            unsigned ahi[4][4];
#pragma unroll
            for (int mt = 0; mt < 4; mt++) {
                const float2* ap = &ws[(tl * 8 + lr) * 132 + wm * 64 + mt * 16 + lq];
                ahi[mt][0] = __float_as_uint(ap[0].x);
                ahi[mt][1] = __float_as_uint(ap[8].x);
                ahi[mt][2] = __float_as_uint(ap[4 * 132].x);
                ahi[mt][3] = __float_as_uint(ap[4 * 132 + 8].x);
            }
#pragma unroll
            for (int nt = 0; nt < NT; nt++) {
                const int x = xb + nt * 8 + lq;
                const float* bp = &ins[(lr * 3 + (yl + 1 - a)) * ISTR + x + 1 - c];
                unsigned bh0 = tf32cvt(bp[0]), bh1 = tf32cvt(bp[4 * 3 * ISTR]);
#pragma unroll
                for (int mt = 0; mt < 4; mt++)
                    mma8(acc[mt][nt], ahi[mt], bh0, bh1);
            }
        }
        __syncthreads();
    }
    const int HOUT = 2 * HIN;
    const int oy = 2 * (y0 + yl) + py;
#pragma unroll
    for (int mt = 0; mt < 4; mt++) {
        const int oc = ocb + wm * 64 + mt * 16 + lq;
        const float b0v = bias[oc], b1v = bias[oc + 8];
#pragma unroll
        for (int nt = 0; nt < NT; nt++) {
            const int x = xb + nt * 8 + 2 * lr;
            const int ox = 2 * x + px;
            float* o0 = out + (((size_t)b * Cout + oc) * HOUT + oy) * HOUT + ox;
            float* o1 = o0 + (size_t)8 * HOUT * HOUT;
            o0[0] = fmaxf(acc[mt][nt][0] + b0v, 0.f);
            o0[2] = fmaxf(acc[mt][nt][1] + b0v, 0.f);
            o1[0] = fmaxf(acc[mt][nt][2] + b1v, 0.f);
            o1[2] = fmaxf(acc[mt][nt][3] + b1v, 0.f);
        }
    }
}
#define DCONV_SMEM(HIN) ((4 * D_WS2 + 2 * 8 * 3 * ((HIN) + 4)) * 4)

// ============================================================================
// Scalar kernels (unchanged)
// ============================================================================
template <int CIN, bool RELU>
__global__ __launch_bounds__(256, 2)
void conv4s2(const float* __restrict__ in, const float* __restrict__ wt,
             const float* __restrict__ bias, float* __restrict__ out,
             int Cout, int Hin, int Win, int Hout, int Wout, int tilesX) {
    __shared__ float ish[34 * 36];
    __shared__ float wsh[64 * 16];
    const int tile = blockIdx.x;
    const int tx0 = (tile % tilesX) * 16, ty0 = (tile / tilesX) * 16;
    const int ocb = blockIdx.y * 64, b = blockIdx.z;
    const int tid = threadIdx.x, og = tid >> 5, sp = tid & 31;
    const int r = sp >> 1, cb = (sp & 1) * 8;
    float acc[8][8];
#pragma unroll
    for (int o = 0; o < 8; o++) {
        float bv = bias[ocb + og * 8 + o];
#pragma unroll
        for (int j = 0; j < 8; j++) acc[o][j] = bv;
    }
    const int iy0 = ty0 * 2 - 1, ix0 = tx0 * 2 - 1;
    const float* inB = in + ((size_t)b * CIN) * Hin * Win;
    for (int ic = 0; ic < CIN; ic++) {
        const float* inC = inB + (size_t)ic * Hin * Win;
        for (int idx = tid; idx < 34 * 34; idx += 256) {
            int py = idx / 34, px = idx - py * 34;
            int iy = iy0 + py, ix = ix0 + px;
            float v = 0.f;
            if ((unsigned)iy < (unsigned)Hin && (unsigned)ix < (unsigned)Win)
                v = inC[iy * Win + ix];
            ish[py * 36 + px] = v;
        }
        const float* wC = wt + (ic * Cout + ocb) * 16;
        for (int idx = tid; idx < 1024; idx += 256) wsh[idx] = wC[idx];
        __syncthreads();
#pragma unroll
        for (int ky = 0; ky < 4; ky++) {
            const float* rp = &ish[(2 * r + ky) * 36 + 2 * cb];
            float4 v0 = *(const float4*)(rp);
            float4 v1 = *(const float4*)(rp + 4);
            float4 v2 = *(const float4*)(rp + 8);
            float4 v3 = *(const float4*)(rp + 12);
            float4 v4 = *(const float4*)(rp + 16);
            float riv[20] = {v0.x, v0.y, v0.z, v0.w, v1.x, v1.y, v1.z, v1.w,
                             v2.x, v2.y, v2.z, v2.w, v3.x, v3.y, v3.z, v3.w,
                             v4.x, v4.y, v4.z, v4.w};
#pragma unroll
            for (int kx = 0; kx < 4; kx++) {
                const int t = ky * 4 + kx;
                float wv[8];
#pragma unroll
                for (int o = 0; o < 8; o++) wv[o] = wsh[(og * 8 + o) * 16 + t];
#pragma unroll
                for (int o = 0; o < 8; o++)
#pragma unroll
                    for (int j = 0; j < 8; j++)
                        acc[o][j] = fmaf(wv[o], riv[kx + 2 * j], acc[o][j]);
            }
        }
        __syncthreads();
    }
    const int oy = ty0 + r, oxb = tx0 + cb;
#pragma unroll
    for (int o = 0; o < 8; o++) {
        float* op = out + (((size_t)b * Cout + ocb + og * 8 + o) * Hout + oy) * Wout + oxb;
        float tmp[8];
#pragma unroll
        for (int j = 0; j < 8; j++)
            tmp[j] = RELU ? fmaxf(acc[o][j], 0.f) : acc[o][j];
        *(float4*)op       = make_float4(tmp[0], tmp[1], tmp[2], tmp[3]);
        *(float4*)(op + 4) = make_float4(tmp[4], tmp[5], tmp[6], tmp[7]);
    }
}

__global__ __launch_bounds__(128, 4)
void dconv3out(const float* __restrict__ in, const float* __restrict__ wt,
               const float* __restrict__ bias, float* __restrict__ out, int tilesX) {
    const int Cin = 128, Hin = 128, Win = 128, Hout = 256, Wout = 256;
    __shared__ float ish[4][18 * 19];
    __shared__ float wsh[4][3 * 16];
    const int tile = blockIdx.x;
    const int ox0 = (tile % tilesX) * 32, oy0 = (tile / tilesX) * 32;
    const int b = blockIdx.y;
    const int tid = threadIdx.x, q = tid >> 5;
    const int py = q >> 1, px = q & 1;
    const int sp = tid & 31, ry = sp >> 1, ch = (sp & 1) * 8;
    float acc[3][8];
#pragma unroll
    for (int o = 0; o < 3; o++) {
        float bv = bias[o];
#pragma unroll
        for (int j = 0; j < 8; j++) acc[o][j] = bv;
    }
    const int iy0 = oy0 >> 1, ix0 = ox0 >> 1;
    const int kp = 1 - py, kq = 1 - px;
    for (int ic0 = 0; ic0 < Cin; ic0 += 4) {
        for (int idx = tid; idx < 4 * 324; idx += 128) {
            int icc = idx / 324, p = idx - icc * 324;
            int piy = p / 18, pix = p - piy * 18;
            int iy = iy0 - 1 + piy, ix = ix0 - 1 + pix;
            float v = 0.f;
            if ((unsigned)iy < (unsigned)Hin && (unsigned)ix < (unsigned)Win)
                v = in[(((size_t)b * Cin + ic0 + icc) * Hin + iy) * Win + ix];
            ish[icc][piy * 19 + pix] = v;
        }
        for (int idx = tid; idx < 4 * 48; idx += 128) {
            int icc = idx / 48, rmd = idx - icc * 48;
            wsh[icc][rmd] = wt[(ic0 + icc) * 48 + rmd];
        }
        __syncthreads();
#pragma unroll
        for (int icc = 0; icc < 4; icc++) {
#pragma unroll
            for (int a = 0; a < 2; a++) {
                const int ky = kp + 2 * a;
                const int liy = ry + 1 + py - a;
                float iv[10];
                const int base = liy * 19 + ch + px;
#pragma unroll
                for (int j = 0; j < 10; j++) iv[j] = ish[icc][base + j];
#pragma unroll
                for (int c = 0; c < 2; c++) {
                    const int kx = kq + 2 * c;
                    const int t = ky * 4 + kx;
                    const int off = 1 - c;
                    float wv[3];
#pragma unroll
                    for (int o = 0; o < 3; o++) wv[o] = wsh[icc][o * 16 + t];
#pragma unroll
                    for (int o = 0; o < 3; o++)
#pragma unroll
                        for (int j = 0; j < 8; j++)
                            acc[o][j] = fmaf(wv[o], iv[j + off], acc[o][j]);
                }
            }
        }
        __syncthreads();
    }
    const int oy = oy0 + 2 * ry + py;
#pragma unroll
    for (int o = 0; o < 3; o++) {
        float* op = out + (((size_t)b * 3 + o) * Hout + oy) * Wout + ox0 + px + 2 * ch;
#pragma unroll
        for (int j = 0; j < 8; j++) op[2 * j] = acc[o][j];
    }
}

__global__ __launch_bounds__(128, 8)
void vqk(const float* __restrict__ ze, const float* __restrict__ emb,
         float* __restrict__ zq, float* __restrict__ idxf) {
    __shared__ __align__(16) float esh[64 * 64];
    __shared__ float en[64];
    const int row = blockIdx.x * 128 + threadIdx.x;
    float f[64];
    const float4* fp = (const float4*)(ze + (size_t)row * 64);
#pragma unroll
    for (int i = 0; i < 16; i++) {
        float4 v = fp[i];
        f[4 * i] = v.x; f[4 * i + 1] = v.y; f[4 * i + 2] = v.z; f[4 * i + 3] = v.w;
    }
    float fn = 0.f;
#pragma unroll
    for (int d = 0; d < 64; d++) fn = fmaf(f[d], f[d], fn);
    float best = 3.4e38f;
    int bidx = 0;
    for (int cb = 0; cb < 512; cb += 64) {
        __syncthreads();
        const float4* src = (const float4*)(emb + (size_t)cb * 64);
        for (int i = threadIdx.x; i < 1024; i += 128)
            ((float4*)esh)[i] = src[i];
        __syncthreads();
        if (threadIdx.x < 64) {
            float s = 0.f;
            const float* e = esh + threadIdx.x * 64;
#pragma unroll
            for (int d = 0; d < 64; d++) s = fmaf(e[d], e[d], s);
            en[threadIdx.x] = s;
        }
        __syncthreads();
        for (int c = 0; c < 64; c++) {
            const float4* ev = (const float4*)(esh + c * 64);
            float dot = 0.f;
#pragma unroll
            for (int i = 0; i < 16; i++) {
                float4 e = ev[i];
                dot = fmaf(f[4 * i], e.x, dot);
                dot = fmaf(f[4 * i + 1], e.y, dot);
                dot = fmaf(f[4 * i + 2], e.z, dot);
                dot = fmaf(f[4 * i + 3], e.w, dot);
            }
            float sc = fn - 2.f * dot + en[c];
            if (sc < best) { best = sc; bidx = cb + c; }
        }
    }
    idxf[row] = (float)bidx;
    const float4* ep = (const float4*)(emb + (size_t)bidx * 64);
    float4* qp = (float4*)(zq + (size_t)row * 64);
#pragma unroll
    for (int i = 0; i < 16; i++) qp[i] = ep[i];
}

// ---------------------------------------------------------------------------
extern "C" void kernel_launch(void* const* d_in, const int* in_sizes, int n_in,
                              void* d_out, int out_size) {
    (void)in_sizes; (void)n_in;
    const float* x   = (const float*)d_in[0];
    const float* w1  = (const float*)d_in[1];
    const float* b1  = (const float*)d_in[2];
    const float* w2  = (const float*)d_in[3];
    const float* b2  = (const float*)d_in[4];
    const float* w3  = (const float*)d_in[5];
    const float* b3  = (const float*)d_in[6];
    const float* d1w = (const float*)d_in[7];
    const float* d1b = (const float*)d_in[8];
    const float* d2w = (const float*)d_in[9];
    const float* d2b = (const float*)d_in[10];
    const float* d3w = (const float*)d_in[11];
    const float* d3b = (const float*)d_in[12];
    const float* emb = (const float*)d_in[13];

    float *h1, *h2, *g1, *g2, *ze, *zq, *idxf, *wt1;
    float2 *w2s, *w3s, *d2s, *d1s;
    cudaGetSymbolAddress((void**)&h1, g_h1);
    cudaGetSymbolAddress((void**)&h2, g_h2);
    cudaGetSymbolAddress((void**)&g1, g_g1);
    cudaGetSymbolAddress((void**)&g2, g_g2);
    cudaGetSymbolAddress((void**)&ze, g_ze);
    cudaGetSymbolAddress((void**)&zq, g_zq);
    cudaGetSymbolAddress((void**)&idxf, g_if);
    cudaGetSymbolAddress((void**)&wt1, g_wt1);
    cudaGetSymbolAddress((void**)&w2s, g_w2s);
    cudaGetSymbolAddress((void**)&w3s, g_w3s);
    cudaGetSymbolAddress((void**)&d2s, g_d2s);
    cudaGetSymbolAddress((void**)&d1s, g_d1s);

    float* outF = (float*)d_out;
    const int NX = NBATCH * 3 * 256 * 256;
    const int NZ = NBATCH * 64 * 32 * 32;
    const int NI = 16384;
    if (out_size >= NX + 2 * NZ + NI) {
        ze   = outF + NX;
        zq   = outF + NX + NZ;
        idxf = outF + NX + 2 * NZ;
    }

    static bool attr_done = false;
    if (!attr_done) {
        cudaFuncSetAttribute(conv2_mma, cudaFuncAttributeMaxDynamicSharedMemorySize, C2_SMEM);
        cudaFuncSetAttribute(conv3_mma, cudaFuncAttributeMaxDynamicSharedMemorySize, C3_SMEM);
        cudaFuncSetAttribute(dconv_mma<64, 32>, cudaFuncAttributeMaxDynamicSharedMemorySize, DCONV_SMEM(32));
        cudaFuncSetAttribute(dconv_mma<256, 64>, cudaFuncAttributeMaxDynamicSharedMemorySize, DCONV_SMEM(64));
        attr_done = true;
    }

    wsplit2t<<<2048, 256>>>(w2, w2s);
    wtrans<<<(128 * 3 * 16 + 255) / 256, 256>>>(w1, wt1, 128, 3);
    conv4s2<3, true><<<dim3(64, 2, NBATCH), 256>>>(x, wt1, b1, h1, 128, 256, 256, 128, 128, 8);
    conv2_mma<<<dim3(64, 2, NBATCH), 256, C2_SMEM>>>(h1, w2s, b2, h2);
    wsplit3<<<1024, 256>>>(w3, w3s);
    conv3_mma<<<dim3(4, 1, NBATCH * 4), 256, C3_SMEM>>>(h2, w3s, g2);
    addparts<<<NZ / 256, 256>>>(g2, b3, ze);
    vqk<<<128, 128>>>(ze, emb, zq, idxf);
    wsplitD1<<<1024, 256>>>(d1w, d1s);
    dconv_mma<64, 32><<<dim3(16, 4, NBATCH * 2), 256, DCONV_SMEM(32)>>>(zq, d1s, d1b, g1, 256, 2);
    wsplitD2<<<2048, 256>>>(d2w, d2s);
    dconv_mma<256, 64><<<dim3(32, 4, NBATCH), 256, DCONV_SMEM(64)>>>(g1, d2s, d2b, g2, 128, 1);
    dconv3out<<<dim3(64, NBATCH), 128>>>(g2, d3w, d3b, outF, 8);
}

// round 15
// speedup vs baseline: 1.1088x; 1.1088x over previous
#include <cuda_runtime.h>

#define NBATCH 16

__device__ float g_h1[NBATCH * 128 * 128 * 128];
__device__ float g_h2[NBATCH * 256 * 64 * 64];
__device__ float g_g1[NBATCH * 256 * 64 * 64];
__device__ float g_g2[NBATCH * 128 * 128 * 128];
__device__ float g_ze[NBATCH * 64 * 32 * 32];
__device__ float g_zq[NBATCH * 64 * 32 * 32];
__device__ float g_if[16384];
__device__ float g_wt1[128 * 3 * 16];
__device__ float2 g_w2s[16 * 128 * 256];
__device__ float2 g_w3s[16 * 256 * 64];
__device__ float2 g_d2s[16 * 256 * 128];
__device__ float2 g_d1s[16 * 64 * 256];

__device__ __forceinline__ void tf32split(float v, unsigned& hi, unsigned& lo) {
    unsigned h;
    asm("cvt.rna.tf32.f32 %0,%1;" : "=r"(h) : "f"(v));
    float l = v - __uint_as_float(h);
    unsigned lw;
    asm("cvt.rna.tf32.f32 %0,%1;" : "=r"(lw) : "f"(l));
    hi = h; lo = lw;
}
__device__ __forceinline__ unsigned tf32cvt(float v) {
    unsigned h;
    asm("cvt.rna.tf32.f32 %0,%1;" : "=r"(h) : "f"(v));
    return h;
}
__device__ __forceinline__ float2 splitpack(float v) {
    unsigned h, l;
    tf32split(v, h, l);
    return make_float2(__uint_as_float(h), __uint_as_float(l));
}
__device__ __forceinline__ void mma8(float* c, const unsigned* a, unsigned b0, unsigned b1) {
    asm("mma.sync.aligned.m16n8k8.row.col.f32.tf32.tf32.f32 "
        "{%0,%1,%2,%3},{%4,%5,%6,%7},{%8,%9},{%0,%1,%2,%3};"
        : "+f"(c[0]), "+f"(c[1]), "+f"(c[2]), "+f"(c[3])
        : "r"(a[0]), "r"(a[1]), "r"(a[2]), "r"(a[3]), "r"(b0), "r"(b1));
}
__device__ __forceinline__ void cp_async16cg(unsigned dst, const void* src) {
    asm volatile("cp.async.cg.shared.global [%0], [%1], 16;\n" :: "r"(dst), "l"(src));
}
__device__ __forceinline__ void cp_async4_z(unsigned dst, const void* src, bool pred) {
    int sz = pred ? 4 : 0;
    asm volatile("cp.async.ca.shared.global [%0], [%1], 4, %2;\n" :: "r"(dst), "l"(src), "r"(sz));
}
__device__ __forceinline__ void cp_commit() { asm volatile("cp.async.commit_group;\n"); }
template <int N> __device__ __forceinline__ void cp_wait() {
    asm volatile("cp.async.wait_group %0;\n" :: "n"(N));
}

// -------- weight transforms --------------------------------------------------
__global__ void wtrans(const float* __restrict__ w, float* __restrict__ wo, int Cout, int Cin) {
    int idx = blockIdx.x * 256 + threadIdx.x;
    int total = Cout * Cin * 16;
    if (idx < total) {
        int t = idx & 15, rest = idx >> 4;
        int ic = rest % Cin, oc = rest / Cin;
        wo[(ic * Cout + oc) * 16 + t] = w[idx];
    }
}
__global__ void wsplit2t(const float* __restrict__ w, float2* __restrict__ wo) {
    int idx = blockIdx.x * 256 + threadIdx.x;
    int t = idx & 15, ic = (idx >> 4) & 127, oc = idx >> 11;
    wo[(t * 128 + ic) * 256 + oc] = splitpack(w[idx]);
}
__global__ void wsplit3(const float* __restrict__ w, float2* __restrict__ wo) {
    int idx = blockIdx.x * 256 + threadIdx.x;
    int t = idx & 15, ic = (idx >> 4) & 255, oc = idx >> 12;
    wo[(t * 256 + ic) * 64 + oc] = splitpack(w[idx]);
}
__global__ void wsplitD2(const float* __restrict__ w, float2* __restrict__ wo) {
    int idx = blockIdx.x * 256 + threadIdx.x;
    int t = idx & 15, oc = (idx >> 4) & 127, ic = idx >> 11;
    wo[(t * 256 + ic) * 128 + oc] = splitpack(w[idx]);
}
__global__ void wsplitD1(const float* __restrict__ w, float2* __restrict__ wo) {
    int idx = blockIdx.x * 256 + threadIdx.x;
    int t = idx & 15, oc = (idx >> 4) & 255, ic = idx >> 12;
    wo[(t * 64 + ic) * 256 + oc] = splitpack(w[idx]);
}

// ============================================================================
// conv2 MMA (3-term): 2 rows x 64 cols x 128 oc per CTA (R11 structure).
// ============================================================================
#define C2_WS2 (4 * 8 * 132)
#define C2_INS (8 * 6 * 132)
#define C2_SMEM ((4 * C2_WS2 + C2_INS) * 4)
__global__ __launch_bounds__(256, 2)
void conv2_mma(const float* __restrict__ in, const float2* __restrict__ wt,
               const float* __restrict__ bias, float* __restrict__ out) {
    extern __shared__ float sm[];
    float2* ws0 = (float2*)sm;
    float* ins = sm + 4 * C2_WS2;
    unsigned ws_base = (unsigned)__cvta_generic_to_shared(ws0);
    unsigned in_base = (unsigned)__cvta_generic_to_shared(ins);

    const int oy0 = blockIdx.x * 2;
    const int ocb = blockIdx.y * 128;
    const int b   = blockIdx.z;

    const int tid  = threadIdx.x;
    const int wid  = tid >> 5;
    const int lane = tid & 31;
    const int wm   = wid >> 2;
    const int wn   = wid & 3;
    const int oyl  = wn >> 1;
    const int xb   = (wn & 1) * 32;
    const int lq   = lane >> 2;
    const int lr   = lane & 3;

    float acc[4][4][4];
#pragma unroll
    for (int mt = 0; mt < 4; mt++)
#pragma unroll
        for (int nt = 0; nt < 4; nt++)
#pragma unroll
            for (int i = 0; i < 4; i++) acc[mt][nt][i] = 0.f;

    const int iy0 = oy0 * 2 - 1;
    const float* inB = in + ((size_t)b * 128) * 128 * 128;

    auto stage_in = [&](int ch) {
        for (int idx = tid; idx < 8 * 6 * 132; idx += 256) {
            int icl = idx / 792;
            int rem = idx - icl * 792;
            int r = rem / 132, cc = rem - r * 132;
            int iy = iy0 + r, ix = cc - 1;
            bool ok = (unsigned)iy < 128u && (unsigned)ix < 128u;
            const float* src = inB + ((size_t)(ch * 8 + icl) * 128 + iy) * 128 + ix;
            cp_async4_z(in_base + (unsigned)idx * 4u, src, ok);
        }
        cp_commit();
    };
    auto stage_w = [&](int c, int buf) {   // 16B cp.async.cg, 2 oc per copy
        const int tg = c & 3, ch = c >> 2;
#pragma unroll
        for (int i = 0; i < 8; i++) {
            int idx = tid + i * 256;                  // 0..2047 16B-units
            int oc2 = idx & 63, icl = (idx >> 6) & 7, tl = idx >> 9;
            const float2* src =
                wt + ((size_t)((tg * 4 + tl) * 128 + ch * 8 + icl)) * 256 + ocb + oc2 * 2;
            cp_async16cg(ws_base + (unsigned)(buf * C2_WS2 + (tl * 8 + icl) * 132 + oc2 * 2) * 8u, src);
        }
        cp_commit();
    };

    stage_in(0);
    stage_w(0, 0);
    for (int c = 0; c < 64; c++) {
        const int ch = c >> 2, tg = c & 3;
        if (tg == 0 && c > 0) stage_in(ch);
        if (c < 63) { stage_w(c + 1, (c + 1) & 1); cp_wait<1>(); }
        else cp_wait<0>();
        __syncthreads();

        const float2* ws = ws0 + (c & 1) * C2_WS2;
#pragma unroll
        for (int tapl = 0; tapl < 4; tapl++) {
            const int ky = tg, kx = tapl;
            unsigned ahi[4][4], alo[4][4];
#pragma unroll
            for (int mt = 0; mt < 4; mt++) {
                const float2* ap = &ws[(tapl * 8 + lr) * 132 + wm * 64 + mt * 16 + lq];
                float2 p0 = ap[0], p1 = ap[8], p2 = ap[4 * 132], p3 = ap[4 * 132 + 8];
                ahi[mt][0] = __float_as_uint(p0.x); alo[mt][0] = __float_as_uint(p0.y);
                ahi[mt][1] = __float_as_uint(p1.x); alo[mt][1] = __float_as_uint(p1.y);
                ahi[mt][2] = __float_as_uint(p2.x); alo[mt][2] = __float_as_uint(p2.y);
                ahi[mt][3] = __float_as_uint(p3.x); alo[mt][3] = __float_as_uint(p3.y);
            }
#pragma unroll
            for (int nt = 0; nt < 4; nt++) {
                const int ox = xb + nt * 8 + lq;
                const float* bp = &ins[lr * 792 + (2 * oyl + ky) * 132 + 2 * ox + kx];
                float rb0 = bp[0], rb1 = bp[4 * 792];
                unsigned bh0, bl0, bh1, bl1;
                tf32split(rb0, bh0, bl0);
                tf32split(rb1, bh1, bl1);
#pragma unroll
                for (int mt = 0; mt < 4; mt++) {
                    mma8(acc[mt][nt], ahi[mt], bh0, bh1);
                    mma8(acc[mt][nt], ahi[mt], bl0, bl1);
                    mma8(acc[mt][nt], alo[mt], bh0, bh1);
                }
            }
        }
        __syncthreads();
    }

    const int oy = oy0 + oyl;
#pragma unroll
    for (int mt = 0; mt < 4; mt++) {
        const int oc = ocb + wm * 64 + mt * 16 + lq;
        const float b0v = bias[oc], b1v = bias[oc + 8];
#pragma unroll
        for (int nt = 0; nt < 4; nt++) {
            const int ox = xb + nt * 8 + 2 * lr;
            float* o0 = out + (((size_t)b * 256 + oc) * 64 + oy) * 64 + ox;
            float* o1 = o0 + (size_t)8 * 64 * 64;
            *(float2*)o0 = make_float2(fmaxf(acc[mt][nt][0] + b0v, 0.f),
                                       fmaxf(acc[mt][nt][1] + b0v, 0.f));
            *(float2*)o1 = make_float2(fmaxf(acc[mt][nt][2] + b1v, 0.f),
                                       fmaxf(acc[mt][nt][3] + b1v, 0.f));
        }
    }
}

// ============================================================================
// conv3 MMA (3-term)
// ============================================================================
#define C3_WS2 (4 * 8 * 68)
#define C3_INS (8 * 18 * 68)
#define C3_SMEM ((4 * C3_WS2 + 2 * C3_INS) * 4)
__global__ __launch_bounds__(256, 2)
void conv3_mma(const float* __restrict__ in, const float2* __restrict__ wt,
               float* __restrict__ outp) {
    extern __shared__ float sm[];
    float2* ws0 = (float2*)sm;
    float* ins0 = sm + 4 * C3_WS2;
    unsigned ws_base = (unsigned)__cvta_generic_to_shared(ws0);
    unsigned in_base = (unsigned)__cvta_generic_to_shared(ins0);
    const int r0 = blockIdx.x * 8;
    const int b = blockIdx.z >> 2, slab = blockIdx.z & 3;
    const int tid = threadIdx.x, w = tid >> 5, lane = tid & 31;
    const int lq = lane >> 2, lr = lane & 3;
    float acc[4][4][4];
#pragma unroll
    for (int mt = 0; mt < 4; mt++)
#pragma unroll
        for (int nt = 0; nt < 4; nt++)
#pragma unroll
            for (int i = 0; i < 4; i++) acc[mt][nt][i] = 0.f;
    const int iy0 = r0 * 2 - 1;
    const float* inB = in + ((size_t)b * 256 + slab * 64) * 64 * 64;
    auto stage_in3 = [&](int ch) {
        const int ib = ch & 1;
        for (int idx = tid; idx < 8 * 18 * 66; idx += 256) {
            int icl = idx / 1188, rem = idx - icl * 1188;
            int r = rem / 66, cc = rem - r * 66;
            int iy = iy0 + r, ix = cc - 1;
            bool ok = (unsigned)iy < 64u && (unsigned)ix < 64u;
            const float* src = inB + ((size_t)(ch * 8 + icl) * 64 + iy) * 64 + ix;
            cp_async4_z(in_base + (unsigned)(ib * C3_INS + icl * 1224 + r * 68 + cc) * 4u, src, ok);
        }
    };
    auto stage_w3 = [&](int c, int buf) {   // 16B cg
        const int tg = c & 3, ch = c >> 2;
#pragma unroll
        for (int i = 0; i < 4; i++) {
            int idx = tid + i * 256;                  // 0..1023
            int oc2 = idx & 31, icl = (idx >> 5) & 7, tl = idx >> 8;
            const float2* src = wt + ((size_t)((tg * 4 + tl) * 256 + slab * 64 + ch * 8 + icl)) * 64 + oc2 * 2;
            cp_async16cg(ws_base + (unsigned)(buf * C3_WS2 + (tl * 8 + icl) * 68 + oc2 * 2) * 8u, src);
        }
    };
    stage_in3(0);
    stage_w3(0, 0);
    cp_commit();
    for (int c = 0; c < 32; c++) {
        if (c < 31) {
            if (((c + 1) & 3) == 0) stage_in3((c + 1) >> 2);
            stage_w3(c + 1, (c + 1) & 1);
            cp_commit();
            cp_wait<1>();
        } else cp_wait<0>();
        __syncthreads();
        const int tg = c & 3;
        const float2* ws = ws0 + (c & 1) * C3_WS2;
        const float* ins = ins0 + ((c >> 2) & 1) * C3_INS;
#pragma unroll
        for (int tapl = 0; tapl < 4; tapl++) {
            const int ky = tg, kx = tapl;
            unsigned ahi[4][4], alo[4][4];
#pragma unroll
            for (int mt = 0; mt < 4; mt++) {
                const float2* ap = &ws[(tapl * 8 + lr) * 68 + mt * 16 + lq];
                float2 p0 = ap[0], p1 = ap[8], p2 = ap[4 * 68], p3 = ap[4 * 68 + 8];
                ahi[mt][0] = __float_as_uint(p0.x); alo[mt][0] = __float_as_uint(p0.y);
                ahi[mt][1] = __float_as_uint(p1.x); alo[mt][1] = __float_as_uint(p1.y);
                ahi[mt][2] = __float_as_uint(p2.x); alo[mt][2] = __float_as_uint(p2.y);
                ahi[mt][3] = __float_as_uint(p3.x); alo[mt][3] = __float_as_uint(p3.y);
            }
#pragma unroll
            for (int nt = 0; nt < 4; nt++) {
                const int col = nt * 8 + lq;
                const float* bp = &ins[lr * 1224 + (2 * w + ky) * 68 + 2 * col + kx];
                float rb0 = bp[0], rb1 = bp[4 * 1224];
                unsigned bh0, bl0, bh1, bl1;
                tf32split(rb0, bh0, bl0);
                tf32split(rb1, bh1, bl1);
#pragma unroll
                for (int mt = 0; mt < 4; mt++) {
                    mma8(acc[mt][nt], ahi[mt], bh0, bh1);
                    mma8(acc[mt][nt], ahi[mt], bl0, bl1);
                    mma8(acc[mt][nt], alo[mt], bh0, bh1);
                }
            }
        }
        __syncthreads();
    }
    const int NZ = NBATCH * 64 * 32 * 32;
    float* part = outp + (size_t)slab * NZ;
    const int row = r0 + w;
#pragma unroll
    for (int mt = 0; mt < 4; mt++) {
        const int oc = mt * 16 + lq;
#pragma unroll
        for (int nt = 0; nt < 4; nt++) {
            float* o0 = part + (((size_t)b * 64 + oc) * 32 + row) * 32 + nt * 8 + 2 * lr;
            float* o1 = o0 + (size_t)8 * 32 * 32;
            *(float2*)o0 = make_float2(acc[mt][nt][0], acc[mt][nt][1]);
            *(float2*)o1 = make_float2(acc[mt][nt][2], acc[mt][nt][3]);
        }
    }
}

__global__ void addparts(const float* __restrict__ p, const float* __restrict__ bias,
                         float* __restrict__ ze) {
    const int S = NBATCH * 64 * 32 * 32;
    int i = blockIdx.x * 256 + threadIdx.x;
    float v = p[i] + p[i + S] + p[i + 2 * S] + p[i + 3 * S];
    ze[i] = v + bias[(i >> 10) & 63];
}

// ============================================================================
// dconv MMA (1-term tf32)
// ============================================================================
#define D_WS2 (4 * 8 * 132)
template <int CIN, int HIN>
__global__ __launch_bounds__(256, 2)
void dconv_mma(const float* __restrict__ in, const float2* __restrict__ wt,
               const float* __restrict__ bias, float* __restrict__ out,
               int Cout, int nOcb) {
    const int WROW = HIN + 2;
    const int ISTR = HIN + 4;
    const int IBUF = 8 * 3 * ISTR;
    extern __shared__ float sm[];
    float2* ws0 = (float2*)sm;
    float* ins0 = sm + 4 * D_WS2;
    unsigned ws_base = (unsigned)__cvta_generic_to_shared(ws0);
    unsigned in_base = (unsigned)__cvta_generic_to_shared(ins0);
    const int y0 = blockIdx.x * 2;
    const int py = blockIdx.y >> 1, px = blockIdx.y & 1;
    const int b = blockIdx.z / nOcb;
    const int ocb = (blockIdx.z % nOcb) * 128;
    const int tid = threadIdx.x, wid = tid >> 5, lane = tid & 31;
    const int wm = wid >> 2, wn = wid & 3;
    const int yl = wn >> 1, xb = (wn & 1) * (HIN / 2);
    const int lq = lane >> 2, lr = lane & 3;
    const int NT = HIN / 16, NCH = CIN / 8;
    float acc[4][4][4];
#pragma unroll
    for (int mt = 0; mt < 4; mt++)
#pragma unroll
        for (int nt = 0; nt < 4; nt++)
#pragma unroll
            for (int i = 0; i < 4; i++) acc[mt][nt][i] = 0.f;
    const float* inB = in + ((size_t)b * CIN) * HIN * HIN;
    auto stage = [&](int ch, int buf) {
        for (int idx = tid; idx < 8 * 3 * WROW; idx += 256) {
            int icl = idx / (3 * WROW);
            int rem = idx - icl * 3 * WROW;
            int r = rem / WROW, s = rem - r * WROW;
            int iy = y0 + py - 1 + r;
            int ix = px - 1 + s;
            bool ok = (unsigned)iy < (unsigned)HIN && (unsigned)ix < (unsigned)HIN;
            const float* src = inB + ((size_t)(ch * 8 + icl) * HIN + iy) * HIN + ix;
            cp_async4_z(in_base + (unsigned)(buf * IBUF + (icl * 3 + r) * ISTR + s) * 4u, src, ok);
        }
#pragma unroll
        for (int i = 0; i < 8; i++) {       // 16B cg
            int idx = tid + i * 256;        // 0..2047
            int oc2 = idx & 63, icl = (idx >> 6) & 7, tl = idx >> 9;
            int a = tl >> 1, c2 = tl & 1;
            int t = (1 - py + 2 * a) * 4 + (1 - px + 2 * c2);
            const float2* src = wt + ((size_t)(t * CIN + ch * 8 + icl)) * Cout + ocb + oc2 * 2;
            cp_async16cg(ws_base + (unsigned)(buf * D_WS2 + (tl * 8 + icl) * 132 + oc2 * 2) * 8u, src);
        }
        cp_commit();
    };
    stage(0, 0);
    for (int ch = 0; ch < NCH; ch++) {
        if (ch + 1 < NCH) { stage(ch + 1, (ch + 1) & 1); cp_wait<1>(); }
        else cp_wait<0>();
        __syncthreads();
        const float2* ws = ws0 + (ch & 1) * D_WS2;
        const float* ins = ins0 + (ch & 1) * IBUF;
#pragma unroll
        for (int tl = 0; tl < 4; tl++) {
            const int a = tl >> 1, c = tl & 1;
            unsigned ahi[4][4];
#pragma unroll
            for (int mt = 0; mt < 4; mt++) {
                const float2* ap = &ws[(tl * 8 + lr) * 132 + wm * 64 + mt * 16 + lq];
                ahi[mt][0] = __float_as_uint(ap[0].x);
                ahi[mt][1] = __float_as_uint(ap[8].x);
                ahi[mt][2] = __float_as_uint(ap[4 * 132].x);
                ahi[mt][3] = __float_as_uint(ap[4 * 132 + 8].x);
            }
#pragma unroll
            for (int nt = 0; nt < NT; nt++) {
                const int x = xb + nt * 8 + lq;
                const float* bp = &ins[(lr * 3 + (yl + 1 - a)) * ISTR + x + 1 - c];
                unsigned bh0 = tf32cvt(bp[0]), bh1 = tf32cvt(bp[4 * 3 * ISTR]);
#pragma unroll
                for (int mt = 0; mt < 4; mt++)
                    mma8(acc[mt][nt], ahi[mt], bh0, bh1);
            }
        }
        __syncthreads();
    }
    const int HOUT = 2 * HIN;
    const int oy = 2 * (y0 + yl) + py;
#pragma unroll
    for (int mt = 0; mt < 4; mt++) {
        const int oc = ocb + wm * 64 + mt * 16 + lq;
        const float b0v = bias[oc], b1v = bias[oc + 8];
#pragma unroll
        for (int nt = 0; nt < NT; nt++) {
            const int x = xb + nt * 8 + 2 * lr;
            const int ox = 2 * x + px;
            float* o0 = out + (((size_t)b * Cout + oc) * HOUT + oy) * HOUT + ox;
            float* o1 = o0 + (size_t)8 * HOUT * HOUT;
            o0[0] = fmaxf(acc[mt][nt][0] + b0v, 0.f);
            o0[2] = fmaxf(acc[mt][nt][1] + b0v, 0.f);
            o1[0] = fmaxf(acc[mt][nt][2] + b1v, 0.f);
            o1[2] = fmaxf(acc[mt][nt][3] + b1v, 0.f);
        }
    }
}
#define DCONV_SMEM(HIN) ((4 * D_WS2 + 2 * 8 * 3 * ((HIN) + 4)) * 4)

// ============================================================================
// Scalar kernels (unchanged)
// ============================================================================
template <int CIN, bool RELU>
__global__ __launch_bounds__(256, 2)
void conv4s2(const float* __restrict__ in, const float* __restrict__ wt,
             const float* __restrict__ bias, float* __restrict__ out,
             int Cout, int Hin, int Win, int Hout, int Wout, int tilesX) {
    __shared__ float ish[34 * 36];
    __shared__ float wsh[64 * 16];
    const int tile = blockIdx.x;
    const int tx0 = (tile % tilesX) * 16, ty0 = (tile / tilesX) * 16;
    const int ocb = blockIdx.y * 64, b = blockIdx.z;
    const int tid = threadIdx.x, og = tid >> 5, sp = tid & 31;
    const int r = sp >> 1, cb = (sp & 1) * 8;
    float acc[8][8];
#pragma unroll
    for (int o = 0; o < 8; o++) {
        float bv = bias[ocb + og * 8 + o];
#pragma unroll
        for (int j = 0; j < 8; j++) acc[o][j] = bv;
    }
    const int iy0 = ty0 * 2 - 1, ix0 = tx0 * 2 - 1;
    const float* inB = in + ((size_t)b * CIN) * Hin * Win;
    for (int ic = 0; ic < CIN; ic++) {
        const float* inC = inB + (size_t)ic * Hin * Win;
        for (int idx = tid; idx < 34 * 34; idx += 256) {
            int py = idx / 34, px = idx - py * 34;
            int iy = iy0 + py, ix = ix0 + px;
            float v = 0.f;
            if ((unsigned)iy < (unsigned)Hin && (unsigned)ix < (unsigned)Win)
                v = inC[iy * Win + ix];
            ish[py * 36 + px] = v;
        }
        const float* wC = wt + (ic * Cout + ocb) * 16;
        for (int idx = tid; idx < 1024; idx += 256) wsh[idx] = wC[idx];
        __syncthreads();
#pragma unroll
        for (int ky = 0; ky < 4; ky++) {
            const float* rp = &ish[(2 * r + ky) * 36 + 2 * cb];
            float4 v0 = *(const float4*)(rp);
            float4 v1 = *(const float4*)(rp + 4);
            float4 v2 = *(const float4*)(rp + 8);
            float4 v3 = *(const float4*)(rp + 12);
            float4 v4 = *(const float4*)(rp + 16);
            float riv[20] = {v0.x, v0.y, v0.z, v0.w, v1.x, v1.y, v1.z, v1.w,
                             v2.x, v2.y, v2.z, v2.w, v3.x, v3.y, v3.z, v3.w,
                             v4.x, v4.y, v4.z, v4.w};
#pragma unroll
            for (int kx = 0; kx < 4; kx++) {
                const int t = ky * 4 + kx;
                float wv[8];
#pragma unroll
                for (int o = 0; o < 8; o++) wv[o] = wsh[(og * 8 + o) * 16 + t];
#pragma unroll
                for (int o = 0; o < 8; o++)
#pragma unroll
                    for (int j = 0; j < 8; j++)
                        acc[o][j] = fmaf(wv[o], riv[kx + 2 * j], acc[o][j]);
            }
        }
        __syncthreads();
    }
    const int oy = ty0 + r, oxb = tx0 + cb;
#pragma unroll
    for (int o = 0; o < 8; o++) {
        float* op = out + (((size_t)b * Cout + ocb + og * 8 + o) * Hout + oy) * Wout + oxb;
        float tmp[8];
#pragma unroll
        for (int j = 0; j < 8; j++)
            tmp[j] = RELU ? fmaxf(acc[o][j], 0.f) : acc[o][j];
        *(float4*)op       = make_float4(tmp[0], tmp[1], tmp[2], tmp[3]);
        *(float4*)(op + 4) = make_float4(tmp[4], tmp[5], tmp[6], tmp[7]);
    }
}

__global__ __launch_bounds__(128, 4)
void dconv3out(const float* __restrict__ in, const float* __restrict__ wt,
               const float* __restrict__ bias, float* __restrict__ out, int tilesX) {
    const int Cin = 128, Hin = 128, Win = 128, Hout = 256, Wout = 256;
    __shared__ float ish[4][18 * 19];
    __shared__ float wsh[4][3 * 16];
    const int tile = blockIdx.x;
    const int ox0 = (tile % tilesX) * 32, oy0 = (tile / tilesX) * 32;
    const int b = blockIdx.y;
    const int tid = threadIdx.x, q = tid >> 5;
    const int py = q >> 1, px = q & 1;
    const int sp = tid & 31, ry = sp >> 1, ch = (sp & 1) * 8;
    float acc[3][8];
#pragma unroll
    for (int o = 0; o < 3; o++) {
        float bv = bias[o];
#pragma unroll
        for (int j = 0; j < 8; j++) acc[o][j] = bv;
    }
    const int iy0 = oy0 >> 1, ix0 = ox0 >> 1;
    const int kp = 1 - py, kq = 1 - px;
    for (int ic0 = 0; ic0 < Cin; ic0 += 4) {
        for (int idx = tid; idx < 4 * 324; idx += 128) {
            int icc = idx / 324, p = idx - icc * 324;
            int piy = p / 18, pix = p - piy * 18;
            int iy = iy0 - 1 + piy, ix = ix0 - 1 + pix;
            float v = 0.f;
            if ((unsigned)iy < (unsigned)Hin && (unsigned)ix < (unsigned)Win)
                v = in[(((size_t)b * Cin + ic0 + icc) * Hin + iy) * Win + ix];
            ish[icc][piy * 19 + pix] = v;
        }
        for (int idx = tid; idx < 4 * 48; idx += 128) {
            int icc = idx / 48, rmd = idx - icc * 48;
            wsh[icc][rmd] = wt[(ic0 + icc) * 48 + rmd];
        }
        __syncthreads();
#pragma unroll
        for (int icc = 0; icc < 4; icc++) {
#pragma unroll
            for (int a = 0; a < 2; a++) {
                const int ky = kp + 2 * a;
                const int liy = ry + 1 + py - a;
                float iv[10];
                const int base = liy * 19 + ch + px;
#pragma unroll
                for (int j = 0; j < 10; j++) iv[j] = ish[icc][base + j];
#pragma unroll
                for (int c = 0; c < 2; c++) {
                    const int kx = kq + 2 * c;
                    const int t = ky * 4 + kx;
                    const int off = 1 - c;
                    float wv[3];
#pragma unroll
                    for (int o = 0; o < 3; o++) wv[o] = wsh[icc][o * 16 + t];
#pragma unroll
                    for (int o = 0; o < 3; o++)
#pragma unroll
                        for (int j = 0; j < 8; j++)
                            acc[o][j] = fmaf(wv[o], iv[j + off], acc[o][j]);
                }
            }
        }
        __syncthreads();
    }
    const int oy = oy0 + 2 * ry + py;
#pragma unroll
    for (int o = 0; o < 3; o++) {
        float* op = out + (((size_t)b * 3 + o) * Hout + oy) * Wout + ox0 + px + 2 * ch;
#pragma unroll
        for (int j = 0; j < 8; j++) op[2 * j] = acc[o][j];
    }
}

__global__ __launch_bounds__(128, 8)
void vqk(const float* __restrict__ ze, const float* __restrict__ emb,
         float* __restrict__ zq, float* __restrict__ idxf) {
    __shared__ __align__(16) float esh[64 * 64];
    __shared__ float en[64];
    const int row = blockIdx.x * 128 + threadIdx.x;
    float f[64];
    const float4* fp = (const float4*)(ze + (size_t)row * 64);
#pragma unroll
    for (int i = 0; i < 16; i++) {
        float4 v = fp[i];
        f[4 * i] = v.x; f[4 * i + 1] = v.y; f[4 * i + 2] = v.z; f[4 * i + 3] = v.w;
    }
    float fn = 0.f;
#pragma unroll
    for (int d = 0; d < 64; d++) fn = fmaf(f[d], f[d], fn);
    float best = 3.4e38f;
    int bidx = 0;
    for (int cb = 0; cb < 512; cb += 64) {
        __syncthreads();
        const float4* src = (const float4*)(emb + (size_t)cb * 64);
        for (int i = threadIdx.x; i < 1024; i += 128)
            ((float4*)esh)[i] = src[i];
        __syncthreads();
        if (threadIdx.x < 64) {
            float s = 0.f;
            const float* e = esh + threadIdx.x * 64;
#pragma unroll
            for (int d = 0; d < 64; d++) s = fmaf(e[d], e[d], s);
            en[threadIdx.x] = s;
        }
        __syncthreads();
        for (int c = 0; c < 64; c++) {
            const float4* ev = (const float4*)(esh + c * 64);
            float dot = 0.f;
#pragma unroll
            for (int i = 0; i < 16; i++) {
                float4 e = ev[i];
                dot = fmaf(f[4 * i], e.x, dot);
                dot = fmaf(f[4 * i + 1], e.y, dot);
                dot = fmaf(f[4 * i + 2], e.z, dot);
                dot = fmaf(f[4 * i + 3], e.w, dot);
            }
            float sc = fn - 2.f * dot + en[c];
            if (sc < best) { best = sc; bidx = cb + c; }
        }
    }
    idxf[row] = (float)bidx;
    const float4* ep = (const float4*)(emb + (size_t)bidx * 64);
    float4* qp = (float4*)(zq + (size_t)row * 64);
#pragma unroll
    for (int i = 0; i < 16; i++) qp[i] = ep[i];
}

// ---------------------------------------------------------------------------
extern "C" void kernel_launch(void* const* d_in, const int* in_sizes, int n_in,
                              void* d_out, int out_size) {
    (void)in_sizes; (void)n_in;
    const float* x   = (const float*)d_in[0];
    const float* w1  = (const float*)d_in[1];
    const float* b1  = (const float*)d_in[2];
    const float* w2  = (const float*)d_in[3];
    const float* b2  = (const float*)d_in[4];
    const float* w3  = (const float*)d_in[5];
    const float* b3  = (const float*)d_in[6];
    const float* d1w = (const float*)d_in[7];
    const float* d1b = (const float*)d_in[8];
    const float* d2w = (const float*)d_in[9];
    const float* d2b = (const float*)d_in[10];
    const float* d3w = (const float*)d_in[11];
    const float* d3b = (const float*)d_in[12];
    const float* emb = (const float*)d_in[13];

    float *h1, *h2, *g1, *g2, *ze, *zq, *idxf, *wt1;
    float2 *w2s, *w3s, *d2s, *d1s;
    cudaGetSymbolAddress((void**)&h1, g_h1);
    cudaGetSymbolAddress((void**)&h2, g_h2);
    cudaGetSymbolAddress((void**)&g1, g_g1);
    cudaGetSymbolAddress((void**)&g2, g_g2);
    cudaGetSymbolAddress((void**)&ze, g_ze);
    cudaGetSymbolAddress((void**)&zq, g_zq);
    cudaGetSymbolAddress((void**)&idxf, g_if);
    cudaGetSymbolAddress((void**)&wt1, g_wt1);
    cudaGetSymbolAddress((void**)&w2s, g_w2s);
    cudaGetSymbolAddress((void**)&w3s, g_w3s);
    cudaGetSymbolAddress((void**)&d2s, g_d2s);
    cudaGetSymbolAddress((void**)&d1s, g_d1s);

    float* outF = (float*)d_out;
    const int NX = NBATCH * 3 * 256 * 256;
    const int NZ = NBATCH * 64 * 32 * 32;
    const int NI = 16384;
    if (out_size >= NX + 2 * NZ + NI) {
        ze   = outF + NX;
        zq   = outF + NX + NZ;
        idxf = outF + NX + 2 * NZ;
    }

    static bool attr_done = false;
    if (!attr_done) {
        cudaFuncSetAttribute(conv2_mma, cudaFuncAttributeMaxDynamicSharedMemorySize, C2_SMEM);
        cudaFuncSetAttribute(conv3_mma, cudaFuncAttributeMaxDynamicSharedMemorySize, C3_SMEM);
        cudaFuncSetAttribute(dconv_mma<64, 32>, cudaFuncAttributeMaxDynamicSharedMemorySize, DCONV_SMEM(32));
        cudaFuncSetAttribute(dconv_mma<256, 64>, cudaFuncAttributeMaxDynamicSharedMemorySize, DCONV_SMEM(64));
        attr_done = true;
    }

    wsplit2t<<<2048, 256>>>(w2, w2s);
    wtrans<<<(128 * 3 * 16 + 255) / 256, 256>>>(w1, wt1, 128, 3);
    conv4s2<3, true><<<dim3(64, 2, NBATCH), 256>>>(x, wt1, b1, h1, 128, 256, 256, 128, 128, 8);
    conv2_mma<<<dim3(32, 2, NBATCH), 256, C2_SMEM>>>(h1, w2s, b2, h2);
    wsplit3<<<1024, 256>>>(w3, w3s);
    conv3_mma<<<dim3(4, 1, NBATCH * 4), 256, C3_SMEM>>>(h2, w3s, g2);
    addparts<<<NZ / 256, 256>>>(g2, b3, ze);
    vqk<<<128, 128>>>(ze, emb, zq, idxf);
    wsplitD1<<<1024, 256>>>(d1w, d1s);
    dconv_mma<64, 32><<<dim3(16, 4, NBATCH * 2), 256, DCONV_SMEM(32)>>>(zq, d1s, d1b, g1, 256, 2);
    wsplitD2<<<2048, 256>>>(d2w, d2s);
    dconv_mma<256, 64><<<dim3(32, 4, NBATCH), 256, DCONV_SMEM(64)>>>(g1, d2s, d2b, g2, 128, 1);
    dconv3out<<<dim3(64, NBATCH), 128>>>(g2, d3w, d3b, outF, 8);
}

// round 17
// speedup vs baseline: 1.2698x; 1.1452x over previous
#include <cuda_runtime.h>

#define NBATCH 16

__device__ float g_h1[NBATCH * 128 * 128 * 128];
__device__ float g_h2[NBATCH * 256 * 64 * 64];
__device__ float g_g1[NBATCH * 256 * 64 * 64];
__device__ float g_g2[NBATCH * 128 * 128 * 128];
__device__ float g_ze[NBATCH * 64 * 32 * 32];
__device__ float g_zq[NBATCH * 64 * 32 * 32];
__device__ float g_if[16384];
__device__ float g_wt1[128 * 3 * 16];
__device__ float4 g_w2q[262144];           // conv2 [t16][ch16][klo4][blk2][h2][q64]
__device__ float2 g_w3s[16 * 256 * 64];    // conv3 (R15 layout)
__device__ float4 g_d2q[131072];           // dconv2 [t16][ch32][klo4][q64]
__device__ float4 g_d1q[65536];            // dconv1 [t16][ch8][klo4][q128]

__device__ __forceinline__ void tf32split(float v, unsigned& hi, unsigned& lo) {
    unsigned h;
    asm("cvt.rna.tf32.f32 %0,%1;" : "=r"(h) : "f"(v));
    float l = v - __uint_as_float(h);
    unsigned lw;
    asm("cvt.rna.tf32.f32 %0,%1;" : "=r"(lw) : "f"(l));
    hi = h; lo = lw;
}
__device__ __forceinline__ unsigned tf32cvt(float v) {
    unsigned h;
    asm("cvt.rna.tf32.f32 %0,%1;" : "=r"(h) : "f"(v));
    return h;
}
__device__ __forceinline__ float tf32r(float v) { return __uint_as_float(tf32cvt(v)); }
__device__ __forceinline__ float2 splitpack(float v) {
    unsigned h, l;
    tf32split(v, h, l);
    return make_float2(__uint_as_float(h), __uint_as_float(l));
}
__device__ __forceinline__ void mma8(float* c, const unsigned* a, unsigned b0, unsigned b1) {
    asm("mma.sync.aligned.m16n8k8.row.col.f32.tf32.tf32.f32 "
        "{%0,%1,%2,%3},{%4,%5,%6,%7},{%8,%9},{%0,%1,%2,%3};"
        : "+f"(c[0]), "+f"(c[1]), "+f"(c[2]), "+f"(c[3])
        : "r"(a[0]), "r"(a[1]), "r"(a[2]), "r"(a[3]), "r"(b0), "r"(b1));
}
__device__ __forceinline__ void cp_async16cg(unsigned dst, const void* src) {
    asm volatile("cp.async.cg.shared.global [%0], [%1], 16;\n" :: "r"(dst), "l"(src));
}
__device__ __forceinline__ void cp_async4_z(unsigned dst, const void* src, bool pred) {
    int sz = pred ? 4 : 0;
    asm volatile("cp.async.ca.shared.global [%0], [%1], 4, %2;\n" :: "r"(dst), "l"(src), "r"(sz));
}
__device__ __forceinline__ void cp_commit() { asm volatile("cp.async.commit_group;\n"); }
template <int N> __device__ __forceinline__ void cp_wait() {
    asm volatile("cp.async.wait_group %0;\n" :: "n"(N));
}

// -------- weight transforms --------------------------------------------------
__global__ void wtrans(const float* __restrict__ w, float* __restrict__ wo, int Cout, int Cin) {
    int idx = blockIdx.x * 256 + threadIdx.x;
    int total = Cout * Cin * 16;
    if (idx < total) {
        int t = idx & 15, rest = idx >> 4;
        int ic = rest % Cin, oc = rest / Cin;
        wo[(ic * Cout + oc) * 16 + t] = w[idx];
    }
}
// conv2: pack fragment quads {(klo,oc),(klo,oc+8),(klo+4,oc),(klo+4,oc+8)}, hi/lo planes
__global__ void wsplit2q(const float* __restrict__ w, float4* __restrict__ wo) {
    int idx = blockIdx.x * 256 + threadIdx.x;   // 262144
    int q = idx & 63, h = (idx >> 6) & 1, blk = (idx >> 7) & 1;
    int klo = (idx >> 8) & 3, ch = (idx >> 10) & 15, t = idx >> 14;   // FIXED bit positions
    int oc = blk * 128 + ((q >> 3) << 4) + (q & 7);
    int ic0 = ch * 8 + klo, ic1 = ic0 + 4;
    float2 s00 = splitpack(w[((size_t)oc * 128 + ic0) * 16 + t]);
    float2 s08 = splitpack(w[((size_t)(oc + 8) * 128 + ic0) * 16 + t]);
    float2 s10 = splitpack(w[((size_t)oc * 128 + ic1) * 16 + t]);
    float2 s18 = splitpack(w[((size_t)(oc + 8) * 128 + ic1) * 16 + t]);
    wo[idx] = (h == 0) ? make_float4(s00.x, s08.x, s10.x, s18.x)
                       : make_float4(s00.y, s08.y, s10.y, s18.y);
}
__global__ void wsplit3(const float* __restrict__ w, float2* __restrict__ wo) {
    int idx = blockIdx.x * 256 + threadIdx.x;
    int t = idx & 15, ic = (idx >> 4) & 255, oc = idx >> 12;
    wo[(t * 256 + ic) * 64 + oc] = splitpack(w[idx]);
}
// dconv: pack hi-only fragment quads; w layout [CIN ic][Cout oc][16 t]
__global__ void wsplitDq(const float* __restrict__ w, float4* __restrict__ wo,
                         int CIN, int Cout) {
    int idx = blockIdx.x * 256 + threadIdx.x;
    int QC = Cout >> 1;
    int q = idx % QC;
    int rest = idx / QC;
    int klo = rest & 3; rest >>= 2;
    int ch = rest % (CIN >> 3);
    int t = rest / (CIN >> 3);
    if (t >= 16) return;
    int oc = ((q >> 3) << 4) + (q & 7);
    int ic0 = ch * 8 + klo, ic1 = ic0 + 4;
    float h00 = tf32r(w[((size_t)ic0 * Cout + oc) * 16 + t]);
    float h08 = tf32r(w[((size_t)ic0 * Cout + oc + 8) * 16 + t]);
    float h10 = tf32r(w[((size_t)ic1 * Cout + oc) * 16 + t]);
    float h18 = tf32r(w[((size_t)ic1 * Cout + oc + 8) * 16 + t]);
    wo[idx] = make_float4(h00, h08, h10, h18);
}

// ============================================================================
// conv2 MMA (3-term): 2 rows x 64 cols x 128 oc per CTA; A via LDS.128.
// ============================================================================
#define C2_INS (8 * 6 * 132)
#define C2_SMEM ((4224 * 4 + C2_INS) * 4)
__global__ __launch_bounds__(256, 2)
void conv2_mma(const float* __restrict__ in, const float4* __restrict__ wq,
               const float* __restrict__ bias, float* __restrict__ out) {
    extern __shared__ float sm[];
    float4* ws40 = (float4*)sm;
    float* ins = sm + 4224 * 4;
    unsigned ws_base = (unsigned)__cvta_generic_to_shared(ws40);
    unsigned in_base = (unsigned)__cvta_generic_to_shared(ins);

    const int oy0 = blockIdx.x * 2;
    const int obs = blockIdx.y;
    const int ocb = obs * 128;
    const int b   = blockIdx.z;

    const int tid  = threadIdx.x;
    const int wid  = tid >> 5;
    const int lane = tid & 31;
    const int wm   = wid >> 2;
    const int wn   = wid & 3;
    const int oyl  = wn >> 1;
    const int xb   = (wn & 1) * 32;
    const int lq   = lane >> 2;
    const int lr   = lane & 3;

    float acc[4][4][4];
#pragma unroll
    for (int mt = 0; mt < 4; mt++)
#pragma unroll
        for (int nt = 0; nt < 4; nt++)
#pragma unroll
            for (int i = 0; i < 4; i++) acc[mt][nt][i] = 0.f;

    const int iy0 = oy0 * 2 - 1;
    const float* inB = in + ((size_t)b * 128) * 128 * 128;

    auto stage_in = [&](int ch) {
        for (int idx = tid; idx < 8 * 6 * 132; idx += 256) {
            int icl = idx / 792;
            int rem = idx - icl * 792;
            int r = rem / 132, cc = rem - r * 132;
            int iy = iy0 + r, ix = cc - 1;
            bool ok = (unsigned)iy < 128u && (unsigned)ix < 128u;
            const float* src = inB + ((size_t)(ch * 8 + icl) * 128 + iy) * 128 + ix;
            cp_async4_z(in_base + (unsigned)idx * 4u, src, ok);
        }
        cp_commit();
    };
    auto stage_w = [&](int c, int buf) {
        const int tg = c & 3, ch = c >> 2;
#pragma unroll
        for (int i = 0; i < 8; i++) {
            int idx = tid + i * 256;
            int q = idx & 63, h = (idx >> 6) & 1, klo = (idx >> 7) & 3, tl = idx >> 9;
            int t = tg * 4 + tl;
            const float4* src =
                wq + ((((size_t)(t * 16 + ch) * 4 + klo) * 2 + obs) * 2 + h) * 64 + q;
            unsigned dst = ws_base +
                (unsigned)(buf * 2112 + h * 1056 + (tl * 4 + klo) * 66 + q) * 16u;
            cp_async16cg(dst, src);
        }
        cp_commit();
    };

    stage_in(0);
    stage_w(0, 0);
    for (int c = 0; c < 64; c++) {
        const int ch = c >> 2, tg = c & 3;
        if (tg == 0 && c > 0) stage_in(ch);
        if (c < 63) { stage_w(c + 1, (c + 1) & 1); cp_wait<1>(); }
        else cp_wait<0>();
        __syncthreads();

        const float4* wsH = ws40 + (c & 1) * 2112;
        const float4* wsL = wsH + 1056;
#pragma unroll
        for (int tapl = 0; tapl < 4; tapl++) {
            const int ky = tg, kx = tapl;
            unsigned ahi[4][4], alo[4][4];
#pragma unroll
            for (int mt = 0; mt < 4; mt++) {
                const int fi = (tapl * 4 + lr) * 66 + wm * 32 + mt * 8 + lq;
                float4 fh = wsH[fi];
                float4 fl = wsL[fi];
                ahi[mt][0] = __float_as_uint(fh.x); ahi[mt][1] = __float_as_uint(fh.y);
                ahi[mt][2] = __float_as_uint(fh.z); ahi[mt][3] = __float_as_uint(fh.w);
                alo[mt][0] = __float_as_uint(fl.x); alo[mt][1] = __float_as_uint(fl.y);
                alo[mt][2] = __float_as_uint(fl.z); alo[mt][3] = __float_as_uint(fl.w);
            }
#pragma unroll
            for (int nt = 0; nt < 4; nt++) {
                const int ox = xb + nt * 8 + lq;
                const float* bp = &ins[lr * 792 + (2 * oyl + ky) * 132 + 2 * ox + kx];
                float rb0 = bp[0], rb1 = bp[4 * 792];
                unsigned bh0, bl0, bh1, bl1;
                tf32split(rb0, bh0, bl0);
                tf32split(rb1, bh1, bl1);
#pragma unroll
                for (int mt = 0; mt < 4; mt++) {
                    mma8(acc[mt][nt], ahi[mt], bh0, bh1);
                    mma8(acc[mt][nt], ahi[mt], bl0, bl1);
                    mma8(acc[mt][nt], alo[mt], bh0, bh1);
                }
            }
        }
        __syncthreads();
    }

    const int oy = oy0 + oyl;
#pragma unroll
    for (int mt = 0; mt < 4; mt++) {
        const int oc = ocb + wm * 64 + mt * 16 + lq;
        const float b0v = bias[oc], b1v = bias[oc + 8];
#pragma unroll
        for (int nt = 0; nt < 4; nt++) {
            const int ox = xb + nt * 8 + 2 * lr;
            float* o0 = out + (((size_t)b * 256 + oc) * 64 + oy) * 64 + ox;
            float* o1 = o0 + (size_t)8 * 64 * 64;
            *(float2*)o0 = make_float2(fmaxf(acc[mt][nt][0] + b0v, 0.f),
                                       fmaxf(acc[mt][nt][1] + b0v, 0.f));
            *(float2*)o1 = make_float2(fmaxf(acc[mt][nt][2] + b1v, 0.f),
                                       fmaxf(acc[mt][nt][3] + b1v, 0.f));
        }
    }
}

// ============================================================================
// conv3 MMA (3-term, R15 unchanged)
// ============================================================================
#define C3_WS2 (4 * 8 * 68)
#define C3_INS (8 * 18 * 68)
#define C3_SMEM ((4 * C3_WS2 + 2 * C3_INS) * 4)
__global__ __launch_bounds__(256, 2)
void conv3_mma(const float* __restrict__ in, const float2* __restrict__ wt,
               float* __restrict__ outp) {
    extern __shared__ float sm[];
    float2* ws0 = (float2*)sm;
    float* ins0 = sm + 4 * C3_WS2;
    unsigned ws_base = (unsigned)__cvta_generic_to_shared(ws0);
    unsigned in_base = (unsigned)__cvta_generic_to_shared(ins0);
    const int r0 = blockIdx.x * 8;
    const int b = blockIdx.z >> 2, slab = blockIdx.z & 3;
    const int tid = threadIdx.x, w = tid >> 5, lane = tid & 31;
    const int lq = lane >> 2, lr = lane & 3;
    float acc[4][4][4];
#pragma unroll
    for (int mt = 0; mt < 4; mt++)
#pragma unroll
        for (int nt = 0; nt < 4; nt++)
#pragma unroll
            for (int i = 0; i < 4; i++) acc[mt][nt][i] = 0.f;
    const int iy0 = r0 * 2 - 1;
    const float* inB = in + ((size_t)b * 256 + slab * 64) * 64 * 64;
    auto stage_in3 = [&](int ch) {
        const int ib = ch & 1;
        for (int idx = tid; idx < 8 * 18 * 66; idx += 256) {
            int icl = idx / 1188, rem = idx - icl * 1188;
            int r = rem / 66, cc = rem - r * 66;
            int iy = iy0 + r, ix = cc - 1;
            bool ok = (unsigned)iy < 64u && (unsigned)ix < 64u;
            const float* src = inB + ((size_t)(ch * 8 + icl) * 64 + iy) * 64 + ix;
            cp_async4_z(in_base + (unsigned)(ib * C3_INS + icl * 1224 + r * 68 + cc) * 4u, src, ok);
        }
    };
    auto stage_w3 = [&](int c, int buf) {
        const int tg = c & 3, ch = c >> 2;
#pragma unroll
        for (int i = 0; i < 4; i++) {
            int idx = tid + i * 256;
            int oc2 = idx & 31, icl = (idx >> 5) & 7, tl = idx >> 8;
            const float2* src = wt + ((size_t)((tg * 4 + tl) * 256 + slab * 64 + ch * 8 + icl)) * 64 + oc2 * 2;
            cp_async16cg(ws_base + (unsigned)(buf * C3_WS2 + (tl * 8 + icl) * 68 + oc2 * 2) * 8u, src);
        }
    };
    stage_in3(0);
    stage_w3(0, 0);
    cp_commit();
    for (int c = 0; c < 32; c++) {
        if (c < 31) {
            if (((c + 1) & 3) == 0) stage_in3((c + 1) >> 2);
            stage_w3(c + 1, (c + 1) & 1);
            cp_commit();
            cp_wait<1>();
        } else cp_wait<0>();
        __syncthreads();
        const int tg = c & 3;
        const float2* ws = ws0 + (c & 1) * C3_WS2;
        const float* ins = ins0 + ((c >> 2) & 1) * C3_INS;
#pragma unroll
        for (int tapl = 0; tapl < 4; tapl++) {
            const int ky = tg, kx = tapl;
            unsigned ahi[4][4], alo[4][4];
#pragma unroll
            for (int mt = 0; mt < 4; mt++) {
                const float2* ap = &ws[(tapl * 8 + lr) * 68 + mt * 16 + lq];
                float2 p0 = ap[0], p1 = ap[8], p2 = ap[4 * 68], p3 = ap[4 * 68 + 8];
                ahi[mt][0] = __float_as_uint(p0.x); alo[mt][0] = __float_as_uint(p0.y);
                ahi[mt][1] = __float_as_uint(p1.x); alo[mt][1] = __float_as_uint(p1.y);
                ahi[mt][2] = __float_as_uint(p2.x); alo[mt][2] = __float_as_uint(p2.y);
                ahi[mt][3] = __float_as_uint(p3.x); alo[mt][3] = __float_as_uint(p3.y);
            }
#pragma unroll
            for (int nt = 0; nt < 4; nt++) {
                const int col = nt * 8 + lq;
                const float* bp = &ins[lr * 1224 + (2 * w + ky) * 68 + 2 * col + kx];
                float rb0 = bp[0], rb1 = bp[4 * 1224];
                unsigned bh0, bl0, bh1, bl1;
                tf32split(rb0, bh0, bl0);
                tf32split(rb1, bh1, bl1);
#pragma unroll
                for (int mt = 0; mt < 4; mt++) {
                    mma8(acc[mt][nt], ahi[mt], bh0, bh1);
                    mma8(acc[mt][nt], ahi[mt], bl0, bl1);
                    mma8(acc[mt][nt], alo[mt], bh0, bh1);
                }
            }
        }
        __syncthreads();
    }
    const int NZ = NBATCH * 64 * 32 * 32;
    float* part = outp + (size_t)slab * NZ;
    const int row = r0 + w;
#pragma unroll
    for (int mt = 0; mt < 4; mt++) {
        const int oc = mt * 16 + lq;
#pragma unroll
        for (int nt = 0; nt < 4; nt++) {
            float* o0 = part + (((size_t)b * 64 + oc) * 32 + row) * 32 + nt * 8 + 2 * lr;
            float* o1 = o0 + (size_t)8 * 32 * 32;
            *(float2*)o0 = make_float2(acc[mt][nt][0], acc[mt][nt][1]);
            *(float2*)o1 = make_float2(acc[mt][nt][2], acc[mt][nt][3]);
        }
    }
}

__global__ void addparts(const float* __restrict__ p, const float* __restrict__ bias,
                         float* __restrict__ ze) {
    const int S = NBATCH * 64 * 32 * 32;
    int i = blockIdx.x * 256 + threadIdx.x;
    float v = p[i] + p[i + S] + p[i + 2 * S] + p[i + 3 * S];
    ze[i] = v + bias[(i >> 10) & 63];
}

// ============================================================================
// dconv MMA (1-term tf32): A fragment = ONE LDS.128 (k-paired quads).
// ============================================================================
template <int CIN, int HIN>
__global__ __launch_bounds__(256, 2)
void dconv_mma(const float* __restrict__ in, const float4* __restrict__ wq,
               const float* __restrict__ bias, float* __restrict__ out,
               int Cout, int nOcb) {
    const int WROW = HIN + 2;
    const int ISTR = HIN + 4;
    const int IBUF = 8 * 3 * ISTR;
    extern __shared__ float sm[];
    float4* ws40 = (float4*)sm;
    float* ins0 = sm + 2112 * 4;
    unsigned ws_base = (unsigned)__cvta_generic_to_shared(ws40);
    unsigned in_base = (unsigned)__cvta_generic_to_shared(ins0);
    const int y0 = blockIdx.x * 2;
    const int py = blockIdx.y >> 1, px = blockIdx.y & 1;
    const int b = blockIdx.z / nOcb;
    const int ocb = (blockIdx.z % nOcb) * 128;
    const int tid = threadIdx.x, wid = tid >> 5, lane = tid & 31;
    const int wm = wid >> 2, wn = wid & 3;
    const int yl = wn >> 1, xb = (wn & 1) * (HIN / 2);
    const int lq = lane >> 2, lr = lane & 3;
    const int NT = HIN / 16, NCH = CIN / 8;
    float acc[4][4][4];
#pragma unroll
    for (int mt = 0; mt < 4; mt++)
#pragma unroll
        for (int nt = 0; nt < 4; nt++)
#pragma unroll
            for (int i = 0; i < 4; i++) acc[mt][nt][i] = 0.f;
    const float* inB = in + ((size_t)b * CIN) * HIN * HIN;
    auto stage = [&](int ch, int buf) {
        for (int idx = tid; idx < 8 * 3 * WROW; idx += 256) {
            int icl = idx / (3 * WROW);
            int rem = idx - icl * 3 * WROW;
            int r = rem / WROW, s = rem - r * WROW;
            int iy = y0 + py - 1 + r;
            int ix = px - 1 + s;
            bool ok = (unsigned)iy < (unsigned)HIN && (unsigned)ix < (unsigned)HIN;
            const float* src = inB + ((size_t)(ch * 8 + icl) * HIN + iy) * HIN + ix;
            cp_async4_z(in_base + (unsigned)(buf * IBUF + (icl * 3 + r) * ISTR + s) * 4u, src, ok);
        }
#pragma unroll
        for (int i = 0; i < 4; i++) {
            int idx = tid + i * 256;
            int q = idx & 63, klo = (idx >> 6) & 3, tl = idx >> 8;
            int a = tl >> 1, c2 = tl & 1;
            int t = (1 - py + 2 * a) * 4 + (1 - px + 2 * c2);
            const float4* src = wq + ((size_t)(t * (CIN / 8) + ch) * 4 + klo) * (Cout / 2)
                                + (ocb >> 1) + q;
            cp_async16cg(ws_base + (unsigned)(buf * 1056 + (tl * 4 + klo) * 66 + q) * 16u, src);
        }
        cp_commit();
    };
    stage(0, 0);
    for (int ch = 0; ch < NCH; ch++) {
        if (ch + 1 < NCH) { stage(ch + 1, (ch + 1) & 1); cp_wait<1>(); }
        else cp_wait<0>();
        __syncthreads();
        const float4* ws4 = ws40 + (ch & 1) * 1056;
        const float* ins = ins0 + (ch & 1) * IBUF;
#pragma unroll
        for (int tl = 0; tl < 4; tl++) {
            const int a = tl >> 1, c = tl & 1;
            unsigned ahi[4][4];
#pragma unroll
            for (int mt = 0; mt < 4; mt++) {
                float4 f = ws4[(tl * 4 + lr) * 66 + wm * 32 + mt * 8 + lq];
                ahi[mt][0] = __float_as_uint(f.x);
                ahi[mt][1] = __float_as_uint(f.y);
                ahi[mt][2] = __float_as_uint(f.z);
                ahi[mt][3] = __float_as_uint(f.w);
            }
#pragma unroll
            for (int nt = 0; nt < NT; nt++) {
                const int x = xb + nt * 8 + lq;
                const float* bp = &ins[(lr * 3 + (yl + 1 - a)) * ISTR + x + 1 - c];
                unsigned bh0 = tf32cvt(bp[0]), bh1 = tf32cvt(bp[4 * 3 * ISTR]);
#pragma unroll
                for (int mt = 0; mt < 4; mt++)
                    mma8(acc[mt][nt], ahi[mt], bh0, bh1);
            }
        }
        __syncthreads();
    }
    const int HOUT = 2 * HIN;
    const int oy = 2 * (y0 + yl) + py;
#pragma unroll
    for (int mt = 0; mt < 4; mt++) {
        const int oc = ocb + wm * 64 + mt * 16 + lq;
        const float b0v = bias[oc], b1v = bias[oc + 8];
#pragma unroll
        for (int nt = 0; nt < NT; nt++) {
            const int x = xb + nt * 8 + 2 * lr;
            const int ox = 2 * x + px;
            float* o0 = out + (((size_t)b * Cout + oc) * HOUT + oy) * HOUT + ox;
            float* o1 = o0 + (size_t)8 * HOUT * HOUT;
            o0[0] = fmaxf(acc[mt][nt][0] + b0v, 0.f);
            o0[2] = fmaxf(acc[mt][nt][1] + b0v, 0.f);
            o1[0] = fmaxf(acc[mt][nt][2] + b1v, 0.f);
            o1[2] = fmaxf(acc[mt][nt][3] + b1v, 0.f);
        }
    }
}
#define DCONV_SMEM(HIN) (2112 * 16 + 2 * 8 * 3 * ((HIN) + 4) * 4)

// ============================================================================
// Scalar kernels (unchanged)
// ============================================================================
template <int CIN, bool RELU>
__global__ __launch_bounds__(256, 2)
void conv4s2(const float* __restrict__ in, const float* __restrict__ wt,
             const float* __restrict__ bias, float* __restrict__ out,
             int Cout, int Hin, int Win, int Hout, int Wout, int tilesX) {
    __shared__ float ish[34 * 36];
    __shared__ float wsh[64 * 16];
    const int tile = blockIdx.x;
    const int tx0 = (tile % tilesX) * 16, ty0 = (tile / tilesX) * 16;
    const int ocb = blockIdx.y * 64, b = blockIdx.z;
    const int tid = threadIdx.x, og = tid >> 5, sp = tid & 31;
    const int r = sp >> 1, cb = (sp & 1) * 8;
    float acc[8][8];
#pragma unroll
    for (int o = 0; o < 8; o++) {
        float bv = bias[ocb + og * 8 + o];
#pragma unroll
        for (int j = 0; j < 8; j++) acc[o][j] = bv;
    }
    const int iy0 = ty0 * 2 - 1, ix0 = tx0 * 2 - 1;
    const float* inB = in + ((size_t)b * CIN) * Hin * Win;
    for (int ic = 0; ic < CIN; ic++) {
        const float* inC = inB + (size_t)ic * Hin * Win;
        for (int idx = tid; idx < 34 * 34; idx += 256) {
            int py = idx / 34, px = idx - py * 34;
            int iy = iy0 + py, ix = ix0 + px;
            float v = 0.f;
            if ((unsigned)iy < (unsigned)Hin && (unsigned)ix < (unsigned)Win)
                v = inC[iy * Win + ix];
            ish[py * 36 + px] = v;
        }
        const float* wC = wt + (ic * Cout + ocb) * 16;
        for (int idx = tid; idx < 1024; idx += 256) wsh[idx] = wC[idx];
        __syncthreads();
#pragma unroll
        for (int ky = 0; ky < 4; ky++) {
            const float* rp = &ish[(2 * r + ky) * 36 + 2 * cb];
            float4 v0 = *(const float4*)(rp);
            float4 v1 = *(const float4*)(rp + 4);
            float4 v2 = *(const float4*)(rp + 8);
            float4 v3 = *(const float4*)(rp + 12);
            float4 v4 = *(const float4*)(rp + 16);
            float riv[20] = {v0.x, v0.y, v0.z, v0.w, v1.x, v1.y, v1.z, v1.w,
                             v2.x, v2.y, v2.z, v2.w, v3.x, v3.y, v3.z, v3.w,
                             v4.x, v4.y, v4.z, v4.w};
#pragma unroll
            for (int kx = 0; kx < 4; kx++) {
                const int t = ky * 4 + kx;
                float wv[8];
#pragma unroll
                for (int o = 0; o < 8; o++) wv[o] = wsh[(og * 8 + o) * 16 + t];
#pragma unroll
                for (int o = 0; o < 8; o++)
#pragma unroll
                    for (int j = 0; j < 8; j++)
                        acc[o][j] = fmaf(wv[o], riv[kx + 2 * j], acc[o][j]);
            }
        }
        __syncthreads();
    }
    const int oy = ty0 + r, oxb = tx0 + cb;
#pragma unroll
    for (int o = 0; o < 8; o++) {
        float* op = out + (((size_t)b * Cout + ocb + og * 8 + o) * Hout + oy) * Wout + oxb;
        float tmp[8];
#pragma unroll
        for (int j = 0; j < 8; j++)
            tmp[j] = RELU ? fmaxf(acc[o][j], 0.f) : acc[o][j];
        *(float4*)op       = make_float4(tmp[0], tmp[1], tmp[2], tmp[3]);
        *(float4*)(op + 4) = make_float4(tmp[4], tmp[5], tmp[6], tmp[7]);
    }
}

__global__ __launch_bounds__(128, 4)
void dconv3out(const float* __restrict__ in, const float* __restrict__ wt,
               const float* __restrict__ bias, float* __restrict__ out, int tilesX) {
    const int Cin = 128, Hin = 128, Win = 128, Hout = 256, Wout = 256;
    __shared__ float ish[4][18 * 19];
    __shared__ float wsh[4][3 * 16];
    const int tile = blockIdx.x;
    const int ox0 = (tile % tilesX) * 32, oy0 = (tile / tilesX) * 32;
    const int b = blockIdx.y;
    const int tid = threadIdx.x, q = tid >> 5;
    const int py = q >> 1, px = q & 1;
    const int sp = tid & 31, ry = sp >> 1, ch = (sp & 1) * 8;
    float acc[3][8];
#pragma unroll
    for (int o = 0; o < 3; o++) {
        float bv = bias[o];
#pragma unroll
        for (int j = 0; j < 8; j++) acc[o][j] = bv;
    }
    const int iy0 = oy0 >> 1, ix0 = ox0 >> 1;
    const int kp = 1 - py, kq = 1 - px;
    for (int ic0 = 0; ic0 < Cin; ic0 += 4) {
        for (int idx = tid; idx < 4 * 324; idx += 128) {
            int icc = idx / 324, p = idx - icc * 324;
            int piy = p / 18, pix = p - piy * 18;
            int iy = iy0 - 1 + piy, ix = ix0 - 1 + pix;
            float v = 0.f;
            if ((unsigned)iy < (unsigned)Hin && (unsigned)ix < (unsigned)Win)
                v = in[(((size_t)b * Cin + ic0 + icc) * Hin + iy) * Win + ix];
            ish[icc][piy * 19 + pix] = v;
        }
        for (int idx = tid; idx < 4 * 48; idx += 128) {
            int icc = idx / 48, rmd = idx - icc * 48;
            wsh[icc][rmd] = wt[(ic0 + icc) * 48 + rmd];
        }
        __syncthreads();
#pragma unroll
        for (int icc = 0; icc < 4; icc++) {
#pragma unroll
            for (int a = 0; a < 2; a++) {
                const int ky = kp + 2 * a;
                const int liy = ry + 1 + py - a;
                float iv[10];
                const int base = liy * 19 + ch + px;
#pragma unroll
                for (int j = 0; j < 10; j++) iv[j] = ish[icc][base + j];
#pragma unroll
                for (int c = 0; c < 2; c++) {
                    const int kx = kq + 2 * c;
                    const int t = ky * 4 + kx;
                    const int off = 1 - c;
                    float wv[3];
#pragma unroll
                    for (int o = 0; o < 3; o++) wv[o] = wsh[icc][o * 16 + t];
#pragma unroll
                    for (int o = 0; o < 3; o++)
#pragma unroll
                        for (int j = 0; j < 8; j++)
                            acc[o][j] = fmaf(wv[o], iv[j + off], acc[o][j]);
                }
            }
        }
        __syncthreads();
    }
    const int oy = oy0 + 2 * ry + py;
#pragma unroll
    for (int o = 0; o < 3; o++) {
        float* op = out + (((size_t)b * 3 + o) * Hout + oy) * Wout + ox0 + px + 2 * ch;
#pragma unroll
        for (int j = 0; j < 8; j++) op[2 * j] = acc[o][j];
    }
}

__global__ __launch_bounds__(128, 8)
void vqk(const float* __restrict__ ze, const float* __restrict__ emb,
         float* __restrict__ zq, float* __restrict__ idxf) {
    __shared__ __align__(16) float esh[64 * 64];
    __shared__ float en[64];
    const int row = blockIdx.x * 128 + threadIdx.x;
    float f[64];
    const float4* fp = (const float4*)(ze + (size_t)row * 64);
#pragma unroll
    for (int i = 0; i < 16; i++) {
        float4 v = fp[i];
        f[4 * i] = v.x; f[4 * i + 1] = v.y; f[4 * i + 2] = v.z; f[4 * i + 3] = v.w;
    }
    float fn = 0.f;
#pragma unroll
    for (int d = 0; d < 64; d++) fn = fmaf(f[d], f[d], fn);
    float best = 3.4e38f;
    int bidx = 0;
    for (int cb = 0; cb < 512; cb += 64) {
        __syncthreads();
        const float4* src = (const float4*)(emb + (size_t)cb * 64);
        for (int i = threadIdx.x; i < 1024; i += 128)
            ((float4*)esh)[i] = src[i];
        __syncthreads();
        if (threadIdx.x < 64) {
            float s = 0.f;
            const float* e = esh + threadIdx.x * 64;
#pragma unroll
            for (int d = 0; d < 64; d++) s = fmaf(e[d], e[d], s);
            en[threadIdx.x] = s;
        }
        __syncthreads();
        for (int c = 0; c < 64; c++) {
            const float4* ev = (const float4*)(esh + c * 64);
            float dot = 0.f;
#pragma unroll
            for (int i = 0; i < 16; i++) {
                float4 e = ev[i];
                dot = fmaf(f[4 * i], e.x, dot);
                dot = fmaf(f[4 * i + 1], e.y, dot);
                dot = fmaf(f[4 * i + 2], e.z, dot);
                dot = fmaf(f[4 * i + 3], e.w, dot);
            }
            float sc = fn - 2.f * dot + en[c];
            if (sc < best) { best = sc; bidx = cb + c; }
        }
    }
    idxf[row] = (float)bidx;
    const float4* ep = (const float4*)(emb + (size_t)bidx * 64);
    float4* qp = (float4*)(zq + (size_t)row * 64);
#pragma unroll
    for (int i = 0; i < 16; i++) qp[i] = ep[i];
}

// ---------------------------------------------------------------------------
extern "C" void kernel_launch(void* const* d_in, const int* in_sizes, int n_in,
                              void* d_out, int out_size) {
    (void)in_sizes; (void)n_in;
    const float* x   = (const float*)d_in[0];
    const float* w1  = (const float*)d_in[1];
    const float* b1  = (const float*)d_in[2];
    const float* w2  = (const float*)d_in[3];
    const float* b2  = (const float*)d_in[4];
    const float* w3  = (const float*)d_in[5];
    const float* b3  = (const float*)d_in[6];
    const float* d1w = (const float*)d_in[7];
    const float* d1b = (const float*)d_in[8];
    const float* d2w = (const float*)d_in[9];
    const float* d2b = (const float*)d_in[10];
    const float* d3w = (const float*)d_in[11];
    const float* d3b = (const float*)d_in[12];
    const float* emb = (const float*)d_in[13];

    float *h1, *h2, *g1, *g2, *ze, *zq, *idxf, *wt1;
    float2 *w3s;
    float4 *w2q, *d2q, *d1q;
    cudaGetSymbolAddress((void**)&h1, g_h1);
    cudaGetSymbolAddress((void**)&h2, g_h2);
    cudaGetSymbolAddress((void**)&g1, g_g1);
    cudaGetSymbolAddress((void**)&g2, g_g2);
    cudaGetSymbolAddress((void**)&ze, g_ze);
    cudaGetSymbolAddress((void**)&zq, g_zq);
    cudaGetSymbolAddress((void**)&idxf, g_if);
    cudaGetSymbolAddress((void**)&wt1, g_wt1);
    cudaGetSymbolAddress((void**)&w2q, g_w2q);
    cudaGetSymbolAddress((void**)&w3s, g_w3s);
    cudaGetSymbolAddress((void**)&d2q, g_d2q);
    cudaGetSymbolAddress((void**)&d1q, g_d1q);

    float* outF = (float*)d_out;
    const int NX = NBATCH * 3 * 256 * 256;
    const int NZ = NBATCH * 64 * 32 * 32;
    const int NI = 16384;
    if (out_size >= NX + 2 * NZ + NI) {
        ze   = outF + NX;
        zq   = outF + NX + NZ;
        idxf = outF + NX + 2 * NZ;
    }

    static bool attr_done = false;
    if (!attr_done) {
        cudaFuncSetAttribute(conv2_mma, cudaFuncAttributeMaxDynamicSharedMemorySize, C2_SMEM);
        cudaFuncSetAttribute(conv3_mma, cudaFuncAttributeMaxDynamicSharedMemorySize, C3_SMEM);
        cudaFuncSetAttribute(dconv_mma<64, 32>, cudaFuncAttributeMaxDynamicSharedMemorySize, DCONV_SMEM(32));
        cudaFuncSetAttribute(dconv_mma<256, 64>, cudaFuncAttributeMaxDynamicSharedMemorySize, DCONV_SMEM(64));
        attr_done = true;
    }

    wsplit2q<<<1024, 256>>>(w2, w2q);
    wtrans<<<(128 * 3 * 16 + 255) / 256, 256>>>(w1, wt1, 128, 3);
    conv4s2<3, true><<<dim3(64, 2, NBATCH), 256>>>(x, wt1, b1, h1, 128, 256, 256, 128, 128, 8);
    conv2_mma<<<dim3(32, 2, NBATCH), 256, C2_SMEM>>>(h1, w2q, b2, h2);
    wsplit3<<<1024, 256>>>(w3, w3s);
    conv3_mma<<<dim3(4, 1, NBATCH * 4), 256, C3_SMEM>>>(h2, w3s, g2);
    addparts<<<NZ / 256, 256>>>(g2, b3, ze);
    vqk<<<128, 128>>>(ze, emb, zq, idxf);
    wsplitDq<<<256, 256>>>(d1w, d1q, 64, 256);
    dconv_mma<64, 32><<<dim3(16, 4, NBATCH * 2), 256, DCONV_SMEM(32)>>>(zq, d1q, d1b, g1, 256, 2);
    wsplitDq<<<512, 256>>>(d2w, d2q, 256, 128);
    dconv_mma<256, 64><<<dim3(32, 4, NBATCH), 256, DCONV_SMEM(64)>>>(g1, d2q, d2b, g2, 128, 1);
    dconv3out<<<dim3(64, NBATCH), 128>>>(g2, d3w, d3b, outF, 8);
}